// round 2
// baseline (speedup 1.0000x reference)
#include <cuda_runtime.h>
#include <math.h>

// Problem constants
#define B_ 2
#define S_ 2048
#define H_ 2048
#define NH_ 32
#define NKV_ 8
#define DH_ 64
#define NREP_ 4
#define QKVW 3072   // NH*DH + 2*NKV*DH

// Scratch (device globals: no allocation allowed)
__device__ float g_qkv[(size_t)B_ * S_ * QKVW];          // ~50 MB: Q | K | V per token, RoPE applied in place
__device__ float g_attn[(size_t)B_ * S_ * NH_ * DH_];    // ~33 MB: attention output [B,S,NH*DH]

// ---------------------------------------------------------------------------
// SGEMM: C[M,N] = A[M,K] @ W[K,N], fp32, BM=BN=128, BK=16, 8x8 per thread.
// M = gridDim.y*128. All dims used here divide tiles evenly -> no bounds checks.
// ---------------------------------------------------------------------------
__global__ __launch_bounds__(256) void sgemm128(
    const float* __restrict__ A, const float* __restrict__ W,
    float* __restrict__ C, int K, int N, int ldc)
{
    __shared__ float As[16][132];   // A tile transposed [k][m], padded (132 % 4 == 0 keeps float4 alignment)
    __shared__ float Ws[16][128];   // W tile [k][n]

    const int tid = threadIdx.x;
    const int tr = tid >> 4;        // 0..15 -> rows tr*8..
    const int tc = tid & 15;        // 0..15 -> cols tc*8..
    const int mBase = blockIdx.y * 128;
    const int nBase = blockIdx.x * 128;

    float acc[8][8];
#pragma unroll
    for (int i = 0; i < 8; i++)
#pragma unroll
        for (int j = 0; j < 8; j++) acc[i][j] = 0.f;

    const int aRow0 = tid >> 2;          // 0..63
    const int aCol0 = (tid & 3) * 4;     // 0,4,8,12
    const int wRow0 = tid >> 5;          // 0..7
    const int wCol0 = (tid & 31) * 4;    // 0..124

    for (int k0 = 0; k0 < K; k0 += 16) {
#pragma unroll
        for (int li = 0; li < 2; ++li) {
            int ar = aRow0 + li * 64;
            float4 v = *(const float4*)(A + (size_t)(mBase + ar) * K + k0 + aCol0);
            As[aCol0 + 0][ar] = v.x; As[aCol0 + 1][ar] = v.y;
            As[aCol0 + 2][ar] = v.z; As[aCol0 + 3][ar] = v.w;
        }
#pragma unroll
        for (int li = 0; li < 2; ++li) {
            int wr = wRow0 + li * 8;
            float4 v = *(const float4*)(W + (size_t)(k0 + wr) * N + nBase + wCol0);
            *(float4*)&Ws[wr][wCol0] = v;
        }
        __syncthreads();

#pragma unroll
        for (int k = 0; k < 16; k++) {
            float a[8], w[8];
            *(float4*)&a[0] = *(const float4*)&As[k][tr * 8];
            *(float4*)&a[4] = *(const float4*)&As[k][tr * 8 + 4];
            *(float4*)&w[0] = *(const float4*)&Ws[k][tc * 8];
            *(float4*)&w[4] = *(const float4*)&Ws[k][tc * 8 + 4];
#pragma unroll
            for (int i = 0; i < 8; i++)
#pragma unroll
                for (int j = 0; j < 8; j++) acc[i][j] += a[i] * w[j];
        }
        __syncthreads();
    }

#pragma unroll
    for (int i = 0; i < 8; i++) {
        float* cp = C + (size_t)(mBase + tr * 8 + i) * ldc + nBase + tc * 8;
        *(float4*)cp       = make_float4(acc[i][0], acc[i][1], acc[i][2], acc[i][3]);
        *(float4*)(cp + 4) = make_float4(acc[i][4], acc[i][5], acc[i][6], acc[i][7]);
    }
}

// ---------------------------------------------------------------------------
// RoPE in place on Q (heads 0..31) and K (heads 32..39) sections of g_qkv.
// Matches the reference rotate_half convention: pairs (i, i+32) within DH=64.
// inv_freq = 10000^(-2i/64) computed in fp32 via exp2f (no fp64 pipe).
// ---------------------------------------------------------------------------
__global__ void rope_kernel(const int* __restrict__ pos_ids)
{
    const int bs = blockIdx.x;                  // 0..B*S-1
    const float p = (float)pos_ids[bs];
    float* base = g_qkv + (size_t)bs * QKVW;

    // -log2(10000)/32
    const float NEG_L2T_OVER_32 = -0.41524101186092029f;

    for (int idx = threadIdx.x; idx < (NH_ + NKV_) * 32; idx += blockDim.x) {
        const int head = idx >> 5;              // 0..39 (q heads 0..31, k heads 32..39)
        const int i = idx & 31;
        const float inv = exp2f((float)i * NEG_L2T_OVER_32);
        const float ang = p * inv;
        float sv, cv;
        sincosf(ang, &sv, &cv);
        float* hp = base + head * DH_;
        const float x1 = hp[i];
        const float x2 = hp[i + 32];
        hp[i]      = x1 * cv - x2 * sv;
        hp[i + 32] = x2 * cv + x1 * sv;
    }
}

// ---------------------------------------------------------------------------
// Flash attention: grid (S/64, NH, B). 256 threads: 16x16 layout, each thread
// owns a 4x4 microtile (rows tr*4.., cols tc*4..). Online softmax, causal.
// Smem: Qts[d][r] (transposed), KPs = Kts[d][kk] reused as Ps[kk][r], Vs[kk][d].
// Row stride 68 floats (multiple of 4 -> float4-aligned, breaks bank patterns).
// ---------------------------------------------------------------------------
#define PADR 68
#define ATT_SMEM (3 * 64 * PADR * 4)

__global__ __launch_bounds__(256) void flash_attn()
{
    extern __shared__ float sm[];
    float* Qts = sm;                  // [64][PADR]  Q transposed: Qts[d][r]
    float* KPs = sm + 64 * PADR;      // [64][PADR]  Kts[d][kk], later Ps[kk][r]
    float* Vs  = sm + 2 * 64 * PADR;  // [64][PADR]  Vs[kk][d]

    const int qt = blockIdx.x, h = blockIdx.y, b = blockIdx.z;
    const int kh = h >> 2;            // h / NREP_
    const int tid = threadIdx.x;
    const int tr = tid >> 4;          // 0..15
    const int tc = tid & 15;          // 0..15

    const float* Qg = g_qkv + (size_t)b * S_ * QKVW + h * 64;
    const float* Kg = g_qkv + (size_t)b * S_ * QKVW + 2048 + kh * 64;
    const float* Vg = g_qkv + (size_t)b * S_ * QKVW + 2560 + kh * 64;

    // Load Q tile transposed
#pragma unroll
    for (int t = 0; t < 4; t++) {
        int idx = tid + t * 256;                 // 0..1023
        int r = idx >> 4, d4 = (idx & 15) * 4;
        float4 v = *(const float4*)(Qg + (size_t)(qt * 64 + r) * QKVW + d4);
        Qts[(d4 + 0) * PADR + r] = v.x; Qts[(d4 + 1) * PADR + r] = v.y;
        Qts[(d4 + 2) * PADR + r] = v.z; Qts[(d4 + 3) * PADR + r] = v.w;
    }

    float m_run[4], l_run[4], acc[4][4];
#pragma unroll
    for (int i = 0; i < 4; i++) {
        m_run[i] = -INFINITY; l_run[i] = 0.f;
#pragma unroll
        for (int j = 0; j < 4; j++) acc[i][j] = 0.f;
    }

    for (int jt = 0; jt <= qt; ++jt) {
        __syncthreads();  // prior iter's smem reads done (also covers Q-load visibility on iter 0)

        // Load K (transposed) and V tiles
#pragma unroll
        for (int t = 0; t < 4; t++) {
            int idx = tid + t * 256;
            int r = idx >> 4, d4 = (idx & 15) * 4;
            float4 kv = *(const float4*)(Kg + (size_t)(jt * 64 + r) * QKVW + d4);
            KPs[(d4 + 0) * PADR + r] = kv.x; KPs[(d4 + 1) * PADR + r] = kv.y;
            KPs[(d4 + 2) * PADR + r] = kv.z; KPs[(d4 + 3) * PADR + r] = kv.w;
            float4 vv = *(const float4*)(Vg + (size_t)(jt * 64 + r) * QKVW + d4);
            *(float4*)&Vs[r * PADR + d4] = vv;
        }
        __syncthreads();

        // Scores: s[i][j] = sum_d Q[tr*4+i][d] * K[tc*4+j][d]
        float s[4][4];
#pragma unroll
        for (int i = 0; i < 4; i++)
#pragma unroll
            for (int j = 0; j < 4; j++) s[i][j] = 0.f;

#pragma unroll 8
        for (int d = 0; d < 64; ++d) {
            float4 q4 = *(const float4*)&Qts[d * PADR + tr * 4];
            float4 k4 = *(const float4*)&KPs[d * PADR + tc * 4];
            s[0][0] += q4.x * k4.x; s[0][1] += q4.x * k4.y; s[0][2] += q4.x * k4.z; s[0][3] += q4.x * k4.w;
            s[1][0] += q4.y * k4.x; s[1][1] += q4.y * k4.y; s[1][2] += q4.y * k4.z; s[1][3] += q4.y * k4.w;
            s[2][0] += q4.z * k4.x; s[2][1] += q4.z * k4.y; s[2][2] += q4.z * k4.z; s[2][3] += q4.z * k4.w;
            s[3][0] += q4.w * k4.x; s[3][1] += q4.w * k4.y; s[3][2] += q4.w * k4.z; s[3][3] += q4.w * k4.w;
        }

        // Scale + causal mask (index-based, only diagonal tile needs it)
#pragma unroll
        for (int i = 0; i < 4; i++)
#pragma unroll
            for (int j = 0; j < 4; j++) s[i][j] *= 0.125f;
        if (jt == qt) {
            const int qi0 = qt * 64 + tr * 4;
            const int kj0 = jt * 64 + tc * 4;
#pragma unroll
            for (int i = 0; i < 4; i++)
#pragma unroll
                for (int j = 0; j < 4; j++)
                    if (kj0 + j > qi0 + i) s[i][j] = -1e30f;
        }

        // Online softmax: row reductions across the 16 threads of each row group
        float mx[4];
#pragma unroll
        for (int i = 0; i < 4; i++)
            mx[i] = fmaxf(fmaxf(s[i][0], s[i][1]), fmaxf(s[i][2], s[i][3]));
#pragma unroll
        for (int off = 1; off < 16; off <<= 1)
#pragma unroll
            for (int i = 0; i < 4; i++)
                mx[i] = fmaxf(mx[i], __shfl_xor_sync(0xffffffffu, mx[i], off));

        float alpha[4], rs[4];
#pragma unroll
        for (int i = 0; i < 4; i++) {
            float m_new = fmaxf(m_run[i], mx[i]);
            alpha[i] = expf(m_run[i] - m_new);
            m_run[i] = m_new;
            rs[i] = 0.f;
#pragma unroll
            for (int j = 0; j < 4; j++) {
                float pv = expf(s[i][j] - m_new);
                s[i][j] = pv;
                rs[i] += pv;
            }
        }
#pragma unroll
        for (int off = 1; off < 16; off <<= 1)
#pragma unroll
            for (int i = 0; i < 4; i++)
                rs[i] += __shfl_xor_sync(0xffffffffu, rs[i], off);
#pragma unroll
        for (int i = 0; i < 4; i++) {
            l_run[i] = l_run[i] * alpha[i] + rs[i];
#pragma unroll
            for (int j = 0; j < 4; j++) acc[i][j] *= alpha[i];
        }

        __syncthreads();  // all threads done reading KPs as K-tile

        // Write P transposed into KPs: Ps[kk][r]
#pragma unroll
        for (int i = 0; i < 4; i++)
#pragma unroll
            for (int j = 0; j < 4; j++)
                KPs[(tc * 4 + j) * PADR + tr * 4 + i] = s[i][j];
        __syncthreads();

        // O += P @ V
#pragma unroll 8
        for (int kk = 0; kk < 64; ++kk) {
            float4 p4 = *(const float4*)&KPs[kk * PADR + tr * 4];
            float4 v4 = *(const float4*)&Vs[kk * PADR + tc * 4];
            acc[0][0] += p4.x * v4.x; acc[0][1] += p4.x * v4.y; acc[0][2] += p4.x * v4.z; acc[0][3] += p4.x * v4.w;
            acc[1][0] += p4.y * v4.x; acc[1][1] += p4.y * v4.y; acc[1][2] += p4.y * v4.z; acc[1][3] += p4.y * v4.w;
            acc[2][0] += p4.z * v4.x; acc[2][1] += p4.z * v4.y; acc[2][2] += p4.z * v4.z; acc[2][3] += p4.z * v4.w;
            acc[3][0] += p4.w * v4.x; acc[3][1] += p4.w * v4.y; acc[3][2] += p4.w * v4.z; acc[3][3] += p4.w * v4.w;
        }
    }

    // Epilogue: normalize and store to g_attn [B,S,NH*DH]
    float* Og = g_attn + (size_t)b * S_ * (NH_ * DH_) + h * 64;
#pragma unroll
    for (int i = 0; i < 4; i++) {
        const float inv_l = 1.0f / l_run[i];
        const int row = qt * 64 + tr * 4 + i;
        float4 o = make_float4(acc[i][0] * inv_l, acc[i][1] * inv_l,
                               acc[i][2] * inv_l, acc[i][3] * inv_l);
        *(float4*)(Og + (size_t)row * (NH_ * DH_) + tc * 4) = o;
    }
}

// ---------------------------------------------------------------------------
// Launch
// ---------------------------------------------------------------------------
extern "C" void kernel_launch(void* const* d_in, const int* in_sizes, int n_in,
                              void* d_out, int out_size)
{
    const float* X   = (const float*)d_in[0];
    const int*   pos = (const int*)d_in[1];
    const float* Wq  = (const float*)d_in[2];
    const float* Wk  = (const float*)d_in[3];
    const float* Wv  = (const float*)d_in[4];
    const float* Wo  = (const float*)d_in[5];
    float* out = (float*)d_out;

    float* qkv_p = nullptr;
    float* attn_p = nullptr;
    cudaGetSymbolAddress((void**)&qkv_p, g_qkv);
    cudaGetSymbolAddress((void**)&attn_p, g_attn);

    // QKV projections into the packed buffer (ldc = 3072)
    sgemm128<<<dim3(16, 32), 256>>>(X, Wq, qkv_p,        2048, 2048, QKVW);
    sgemm128<<<dim3(4, 32),  256>>>(X, Wk, qkv_p + 2048, 2048, 512,  QKVW);
    sgemm128<<<dim3(4, 32),  256>>>(X, Wv, qkv_p + 2560, 2048, 512,  QKVW);

    // RoPE on Q and K in place
    rope_kernel<<<B_ * S_, 256>>>(pos);

    // Flash attention
    cudaFuncSetAttribute(flash_attn, cudaFuncAttributeMaxDynamicSharedMemorySize, ATT_SMEM);
    flash_attn<<<dim3(S_ / 64, NH_, B_), 256, ATT_SMEM>>>();

    // Output projection
    sgemm128<<<dim3(16, 32), 256>>>(attn_p, Wo, out, 2048, 2048, 2048);
}

// round 5
// speedup vs baseline: 1.7257x; 1.7257x over previous
#include <cuda_runtime.h>
#include <math.h>
#include <stdint.h>

// Problem constants
#define B_ 2
#define S_ 2048
#define H_ 2048
#define NH_ 32
#define NKV_ 8
#define DH_ 64
#define NREP_ 4
#define QKVW 3072   // NH*DH + 2*NKV*DH

// Scratch (device globals: no allocation allowed)
__device__ float g_qkv[(size_t)B_ * S_ * QKVW];          // Q | K | V per token, RoPE applied in place
__device__ float g_attn[(size_t)B_ * S_ * NH_ * DH_];    // attention output [B,S,NH*DH]

// ---------------------------------------------------------------------------
// tf32 tensor-core GEMM: C[M,N] = A[M,K] @ W[K,N]
// BM=BN=128, BK=32, 256 threads (8 warps, warp tile 32x64), mma.m16n8k8,
// cp.async double-buffered smem. M = gridDim.y*128; K%32==0; N%128==0.
// Smem strides: A rows padded to 36 floats, B rows to 132 -> fragment LDS
// addresses (4r+c)%32 are all-distinct within a warp (conflict-free).
// ---------------------------------------------------------------------------
#define ASZ (128 * 36)
#define BSZ (32 * 132)
#define GEMM_SMEM ((2 * ASZ + 2 * BSZ) * 4)

__device__ __forceinline__ void cp_async16(float* smem, const float* gmem) {
    uint32_t s = (uint32_t)__cvta_generic_to_shared(smem);
    asm volatile("cp.async.cg.shared.global [%0], [%1], 16;\n" :: "r"(s), "l"(gmem));
}
#define CP_COMMIT() asm volatile("cp.async.commit_group;\n" ::: "memory")
#define CP_WAIT(n)  asm volatile("cp.async.wait_group %0;\n" :: "n"(n) : "memory")

__device__ __forceinline__ uint32_t f2tf32(float x) {
    uint32_t r;
    asm("cvt.rna.tf32.f32 %0, %1;" : "=r"(r) : "f"(x));
    return r;
}

__device__ __forceinline__ void mma_tf32(float* c, const uint32_t* a, uint32_t b0, uint32_t b1) {
    asm volatile(
        "mma.sync.aligned.m16n8k8.row.col.f32.tf32.tf32.f32 "
        "{%0,%1,%2,%3}, {%4,%5,%6,%7}, {%8,%9}, {%0,%1,%2,%3};"
        : "+f"(c[0]), "+f"(c[1]), "+f"(c[2]), "+f"(c[3])
        : "r"(a[0]), "r"(a[1]), "r"(a[2]), "r"(a[3]), "r"(b0), "r"(b1));
}

__device__ __forceinline__ void gemm_load_tiles(
    const float* __restrict__ A, const float* __restrict__ W,
    float* as, float* bs, int K, int N, int mBase, int nBase, int k0, int tid)
{
#pragma unroll
    for (int i = 0; i < 4; i++) {                    // A tile: 128 x 32
        int idx = tid + i * 256;
        int r = idx >> 3, c4 = (idx & 7) * 4;
        cp_async16(as + r * 36 + c4, A + (size_t)(mBase + r) * K + k0 + c4);
    }
#pragma unroll
    for (int i = 0; i < 4; i++) {                    // B tile: 32 x 128
        int idx = tid + i * 256;
        int r = idx >> 5, n4 = (idx & 31) * 4;
        cp_async16(bs + r * 132 + n4, W + (size_t)(k0 + r) * N + nBase + n4);
    }
}

__global__ __launch_bounds__(256) void gemm_tf32(
    const float* __restrict__ A, const float* __restrict__ W,
    float* __restrict__ C, int K, int N, int ldc)
{
    extern __shared__ float sm[];
    float* asm0 = sm;                // buffers: as0 | as1 | bs0 | bs1
    float* bsm0 = sm + 2 * ASZ;

    const int tid = threadIdx.x;
    const int lane = tid & 31;
    const int wid = tid >> 5;
    const int wm = wid & 3;          // warp m index: 4 -> 32 rows each
    const int wn = wid >> 2;         // warp n index: 2 -> 64 cols each
    const int gid = lane >> 2;       // 0..7
    const int tig = lane & 3;        // 0..3
    const int mBase = blockIdx.y * 128;
    const int nBase = blockIdx.x * 128;

    float acc[2][8][4];
#pragma unroll
    for (int mt = 0; mt < 2; mt++)
#pragma unroll
        for (int nt = 0; nt < 8; nt++)
#pragma unroll
            for (int i = 0; i < 4; i++) acc[mt][nt][i] = 0.f;

    const int T = K >> 5;            // K / 32 tiles

    gemm_load_tiles(A, W, asm0, bsm0, K, N, mBase, nBase, 0, tid);
    CP_COMMIT();

    for (int t = 0; t < T; t++) {
        const int buf = t & 1;
        if (t + 1 < T) {
            gemm_load_tiles(A, W, asm0 + (buf ^ 1) * ASZ, bsm0 + (buf ^ 1) * BSZ,
                            K, N, mBase, nBase, (t + 1) * 32, tid);
            CP_COMMIT();
            CP_WAIT(1);
        } else {
            CP_WAIT(0);
        }
        __syncthreads();

        const float* as = asm0 + buf * ASZ;
        const float* bs = bsm0 + buf * BSZ;

#pragma unroll
        for (int ks = 0; ks < 4; ks++) {
            const int kk = ks * 8;
            uint32_t af[2][4];
#pragma unroll
            for (int mt = 0; mt < 2; mt++) {
                const float* ap = as + (wm * 32 + mt * 16 + gid) * 36 + kk + tig;
                af[mt][0] = f2tf32(ap[0]);
                af[mt][1] = f2tf32(ap[8 * 36]);
                af[mt][2] = f2tf32(ap[4]);
                af[mt][3] = f2tf32(ap[8 * 36 + 4]);
            }
#pragma unroll
            for (int nt = 0; nt < 8; nt++) {
                const float* bp = bs + (kk + tig) * 132 + wn * 64 + nt * 8 + gid;
                uint32_t b0 = f2tf32(bp[0]);
                uint32_t b1 = f2tf32(bp[4 * 132]);
                mma_tf32(acc[0][nt], af[0], b0, b1);
                mma_tf32(acc[1][nt], af[1], b0, b1);
            }
        }
        __syncthreads();
    }

    // Epilogue: float2 stores
#pragma unroll
    for (int mt = 0; mt < 2; mt++) {
#pragma unroll
        for (int nt = 0; nt < 8; nt++) {
            const int r = mBase + wm * 32 + mt * 16 + gid;
            const int c = nBase + wn * 64 + nt * 8 + 2 * tig;
            float2 v0 = make_float2(acc[mt][nt][0], acc[mt][nt][1]);
            float2 v1 = make_float2(acc[mt][nt][2], acc[mt][nt][3]);
            *(float2*)(C + (size_t)r * ldc + c) = v0;
            *(float2*)(C + (size_t)(r + 8) * ldc + c) = v1;
        }
    }
}

// ---------------------------------------------------------------------------
// RoPE in place on Q (heads 0..31) and K (heads 32..39) sections of g_qkv.
// Pairs (i, i+32) within DH=64; inv_freq via exp2f (no fp64 pipe).
// ---------------------------------------------------------------------------
__global__ void rope_kernel(const int* __restrict__ pos_ids)
{
    const int bs = blockIdx.x;                  // 0..B*S-1
    const float p = (float)pos_ids[bs];
    float* base = g_qkv + (size_t)bs * QKVW;

    const float NEG_L2T_OVER_32 = -0.41524101186092029f;   // -log2(10000)/32

    for (int idx = threadIdx.x; idx < (NH_ + NKV_) * 32; idx += blockDim.x) {
        const int head = idx >> 5;              // q heads 0..31, k heads 32..39
        const int i = idx & 31;
        const float inv = exp2f((float)i * NEG_L2T_OVER_32);
        const float ang = p * inv;
        float sv, cv;
        sincosf(ang, &sv, &cv);
        float* hp = base + head * DH_;
        const float x1 = hp[i];
        const float x2 = hp[i + 32];
        hp[i]      = x1 * cv - x2 * sv;
        hp[i + 32] = x2 * cv + x1 * sv;
    }
}

// ---------------------------------------------------------------------------
// Flash attention (fp32): grid (S/64, NH, B). 256 threads, 4x4 microtiles,
// online softmax, causal. Unchanged from round-2 passing version.
// ---------------------------------------------------------------------------
#define PADR 68
#define ATT_SMEM (3 * 64 * PADR * 4)

__global__ __launch_bounds__(256) void flash_attn()
{
    extern __shared__ float smf[];
    float* Qts = smf;                  // [64][PADR]  Q transposed: Qts[d][r]
    float* KPs = smf + 64 * PADR;      // [64][PADR]  Kts[d][kk], later Ps[kk][r]
    float* Vs  = smf + 2 * 64 * PADR;  // [64][PADR]  Vs[kk][d]

    const int qt = blockIdx.x, h = blockIdx.y, b = blockIdx.z;
    const int kh = h >> 2;
    const int tid = threadIdx.x;
    const int tr = tid >> 4;
    const int tc = tid & 15;

    const float* Qg = g_qkv + (size_t)b * S_ * QKVW + h * 64;
    const float* Kg = g_qkv + (size_t)b * S_ * QKVW + 2048 + kh * 64;
    const float* Vg = g_qkv + (size_t)b * S_ * QKVW + 2560 + kh * 64;

#pragma unroll
    for (int t = 0; t < 4; t++) {
        int idx = tid + t * 256;
        int r = idx >> 4, d4 = (idx & 15) * 4;
        float4 v = *(const float4*)(Qg + (size_t)(qt * 64 + r) * QKVW + d4);
        Qts[(d4 + 0) * PADR + r] = v.x; Qts[(d4 + 1) * PADR + r] = v.y;
        Qts[(d4 + 2) * PADR + r] = v.z; Qts[(d4 + 3) * PADR + r] = v.w;
    }

    float m_run[4], l_run[4], acc[4][4];
#pragma unroll
    for (int i = 0; i < 4; i++) {
        m_run[i] = -INFINITY; l_run[i] = 0.f;
#pragma unroll
        for (int j = 0; j < 4; j++) acc[i][j] = 0.f;
    }

    for (int jt = 0; jt <= qt; ++jt) {
        __syncthreads();

#pragma unroll
        for (int t = 0; t < 4; t++) {
            int idx = tid + t * 256;
            int r = idx >> 4, d4 = (idx & 15) * 4;
            float4 kv = *(const float4*)(Kg + (size_t)(jt * 64 + r) * QKVW + d4);
            KPs[(d4 + 0) * PADR + r] = kv.x; KPs[(d4 + 1) * PADR + r] = kv.y;
            KPs[(d4 + 2) * PADR + r] = kv.z; KPs[(d4 + 3) * PADR + r] = kv.w;
            float4 vv = *(const float4*)(Vg + (size_t)(jt * 64 + r) * QKVW + d4);
            *(float4*)&Vs[r * PADR + d4] = vv;
        }
        __syncthreads();

        float s[4][4];
#pragma unroll
        for (int i = 0; i < 4; i++)
#pragma unroll
            for (int j = 0; j < 4; j++) s[i][j] = 0.f;

#pragma unroll 8
        for (int d = 0; d < 64; ++d) {
            float4 q4 = *(const float4*)&Qts[d * PADR + tr * 4];
            float4 k4 = *(const float4*)&KPs[d * PADR + tc * 4];
            s[0][0] += q4.x * k4.x; s[0][1] += q4.x * k4.y; s[0][2] += q4.x * k4.z; s[0][3] += q4.x * k4.w;
            s[1][0] += q4.y * k4.x; s[1][1] += q4.y * k4.y; s[1][2] += q4.y * k4.z; s[1][3] += q4.y * k4.w;
            s[2][0] += q4.z * k4.x; s[2][1] += q4.z * k4.y; s[2][2] += q4.z * k4.z; s[2][3] += q4.z * k4.w;
            s[3][0] += q4.w * k4.x; s[3][1] += q4.w * k4.y; s[3][2] += q4.w * k4.z; s[3][3] += q4.w * k4.w;
        }

#pragma unroll
        for (int i = 0; i < 4; i++)
#pragma unroll
            for (int j = 0; j < 4; j++) s[i][j] *= 0.125f;
        if (jt == qt) {
            const int qi0 = qt * 64 + tr * 4;
            const int kj0 = jt * 64 + tc * 4;
#pragma unroll
            for (int i = 0; i < 4; i++)
#pragma unroll
                for (int j = 0; j < 4; j++)
                    if (kj0 + j > qi0 + i) s[i][j] = -1e30f;
        }

        float mx[4];
#pragma unroll
        for (int i = 0; i < 4; i++)
            mx[i] = fmaxf(fmaxf(s[i][0], s[i][1]), fmaxf(s[i][2], s[i][3]));
#pragma unroll
        for (int off = 1; off < 16; off <<= 1)
#pragma unroll
            for (int i = 0; i < 4; i++)
                mx[i] = fmaxf(mx[i], __shfl_xor_sync(0xffffffffu, mx[i], off));

        float alpha[4], rs[4];
#pragma unroll
        for (int i = 0; i < 4; i++) {
            float m_new = fmaxf(m_run[i], mx[i]);
            alpha[i] = expf(m_run[i] - m_new);
            m_run[i] = m_new;
            rs[i] = 0.f;
#pragma unroll
            for (int j = 0; j < 4; j++) {
                float pv = expf(s[i][j] - m_new);
                s[i][j] = pv;
                rs[i] += pv;
            }
        }
#pragma unroll
        for (int off = 1; off < 16; off <<= 1)
#pragma unroll
            for (int i = 0; i < 4; i++)
                rs[i] += __shfl_xor_sync(0xffffffffu, rs[i], off);
#pragma unroll
        for (int i = 0; i < 4; i++) {
            l_run[i] = l_run[i] * alpha[i] + rs[i];
#pragma unroll
            for (int j = 0; j < 4; j++) acc[i][j] *= alpha[i];
        }

        __syncthreads();

#pragma unroll
        for (int i = 0; i < 4; i++)
#pragma unroll
            for (int j = 0; j < 4; j++)
                KPs[(tc * 4 + j) * PADR + tr * 4 + i] = s[i][j];
        __syncthreads();

#pragma unroll 8
        for (int kk = 0; kk < 64; ++kk) {
            float4 p4 = *(const float4*)&KPs[kk * PADR + tr * 4];
            float4 v4 = *(const float4*)&Vs[kk * PADR + tc * 4];
            acc[0][0] += p4.x * v4.x; acc[0][1] += p4.x * v4.y; acc[0][2] += p4.x * v4.z; acc[0][3] += p4.x * v4.w;
            acc[1][0] += p4.y * v4.x; acc[1][1] += p4.y * v4.y; acc[1][2] += p4.y * v4.z; acc[1][3] += p4.y * v4.w;
            acc[2][0] += p4.z * v4.x; acc[2][1] += p4.z * v4.y; acc[2][2] += p4.z * v4.z; acc[2][3] += p4.z * v4.w;
            acc[3][0] += p4.w * v4.x; acc[3][1] += p4.w * v4.y; acc[3][2] += p4.w * v4.z; acc[3][3] += p4.w * v4.w;
        }
    }

    float* Og = g_attn + (size_t)b * S_ * (NH_ * DH_) + h * 64;
#pragma unroll
    for (int i = 0; i < 4; i++) {
        const float inv_l = 1.0f / l_run[i];
        const int row = qt * 64 + tr * 4 + i;
        float4 o = make_float4(acc[i][0] * inv_l, acc[i][1] * inv_l,
                               acc[i][2] * inv_l, acc[i][3] * inv_l);
        *(float4*)(Og + (size_t)row * (NH_ * DH_) + tc * 4) = o;
    }
}

// ---------------------------------------------------------------------------
// Launch
// ---------------------------------------------------------------------------
extern "C" void kernel_launch(void* const* d_in, const int* in_sizes, int n_in,
                              void* d_out, int out_size)
{
    const float* X   = (const float*)d_in[0];
    const int*   pos = (const int*)d_in[1];
    const float* Wq  = (const float*)d_in[2];
    const float* Wk  = (const float*)d_in[3];
    const float* Wv  = (const float*)d_in[4];
    const float* Wo  = (const float*)d_in[5];
    float* out = (float*)d_out;

    float* qkv_p = nullptr;
    float* attn_p = nullptr;
    cudaGetSymbolAddress((void**)&qkv_p, g_qkv);
    cudaGetSymbolAddress((void**)&attn_p, g_attn);

    cudaFuncSetAttribute(gemm_tf32, cudaFuncAttributeMaxDynamicSharedMemorySize, GEMM_SMEM);
    cudaFuncSetAttribute(flash_attn, cudaFuncAttributeMaxDynamicSharedMemorySize, ATT_SMEM);

    // QKV projections into the packed buffer (ldc = 3072)
    gemm_tf32<<<dim3(16, 32), 256, GEMM_SMEM>>>(X, Wq, qkv_p,        2048, 2048, QKVW);
    gemm_tf32<<<dim3(4, 32),  256, GEMM_SMEM>>>(X, Wk, qkv_p + 2048, 2048, 512,  QKVW);
    gemm_tf32<<<dim3(4, 32),  256, GEMM_SMEM>>>(X, Wv, qkv_p + 2560, 2048, 512,  QKVW);

    // RoPE on Q and K in place
    rope_kernel<<<B_ * S_, 256>>>(pos);

    // Flash attention
    flash_attn<<<dim3(S_ / 64, NH_, B_), 256, ATT_SMEM>>>();

    // Output projection
    gemm_tf32<<<dim3(16, 32), 256, GEMM_SMEM>>>(attn_p, Wo, out, 2048, 2048, 2048);
}

// round 6
// speedup vs baseline: 2.8711x; 1.6638x over previous
#include <cuda_runtime.h>
#include <math.h>
#include <stdint.h>

// Problem constants
#define B_ 2
#define S_ 2048
#define H_ 2048
#define NH_ 32
#define NKV_ 8
#define DH_ 64
#define NREP_ 4
#define QKVW 3072   // NH*DH + 2*NKV*DH

// Scratch (device globals: no allocation allowed)
__device__ float g_qkv[(size_t)B_ * S_ * QKVW];          // Q | K | V per token, RoPE applied in place
__device__ float g_attn[(size_t)B_ * S_ * NH_ * DH_];    // attention output [B,S,NH*DH]

// ---------------------------------------------------------------------------
// Shared helpers: cp.async, tf32 convert, mma.m16n8k8
// ---------------------------------------------------------------------------
__device__ __forceinline__ void cp_async16(float* smem, const float* gmem) {
    uint32_t s = (uint32_t)__cvta_generic_to_shared(smem);
    asm volatile("cp.async.cg.shared.global [%0], [%1], 16;\n" :: "r"(s), "l"(gmem));
}
#define CP_COMMIT() asm volatile("cp.async.commit_group;\n" ::: "memory")
#define CP_WAIT(n)  asm volatile("cp.async.wait_group %0;\n" :: "n"(n) : "memory")

__device__ __forceinline__ uint32_t f2tf32(float x) {
    uint32_t r;
    asm("cvt.rna.tf32.f32 %0, %1;" : "=r"(r) : "f"(x));
    return r;
}

__device__ __forceinline__ void mma_tf32(float* c, const uint32_t* a, uint32_t b0, uint32_t b1) {
    asm volatile(
        "mma.sync.aligned.m16n8k8.row.col.f32.tf32.tf32.f32 "
        "{%0,%1,%2,%3}, {%4,%5,%6,%7}, {%8,%9}, {%0,%1,%2,%3};"
        : "+f"(c[0]), "+f"(c[1]), "+f"(c[2]), "+f"(c[3])
        : "r"(a[0]), "r"(a[1]), "r"(a[2]), "r"(a[3]), "r"(b0), "r"(b1));
}

// ---------------------------------------------------------------------------
// tf32 tensor-core GEMM: C[M,N] = A[M,K] @ W[K,N]  (unchanged from round 5)
// BM=BN=128, BK=32, 256 threads (8 warps, warp tile 32x64), cp.async dbuf.
// ---------------------------------------------------------------------------
#define ASZ (128 * 36)
#define BSZ (32 * 132)
#define GEMM_SMEM ((2 * ASZ + 2 * BSZ) * 4)

__device__ __forceinline__ void gemm_load_tiles(
    const float* __restrict__ A, const float* __restrict__ W,
    float* as, float* bs, int K, int N, int mBase, int nBase, int k0, int tid)
{
#pragma unroll
    for (int i = 0; i < 4; i++) {                    // A tile: 128 x 32
        int idx = tid + i * 256;
        int r = idx >> 3, c4 = (idx & 7) * 4;
        cp_async16(as + r * 36 + c4, A + (size_t)(mBase + r) * K + k0 + c4);
    }
#pragma unroll
    for (int i = 0; i < 4; i++) {                    // B tile: 32 x 128
        int idx = tid + i * 256;
        int r = idx >> 5, n4 = (idx & 31) * 4;
        cp_async16(bs + r * 132 + n4, W + (size_t)(k0 + r) * N + nBase + n4);
    }
}

__global__ __launch_bounds__(256) void gemm_tf32(
    const float* __restrict__ A, const float* __restrict__ W,
    float* __restrict__ C, int K, int N, int ldc)
{
    extern __shared__ float sm[];
    float* asm0 = sm;
    float* bsm0 = sm + 2 * ASZ;

    const int tid = threadIdx.x;
    const int lane = tid & 31;
    const int wid = tid >> 5;
    const int wm = wid & 3;
    const int wn = wid >> 2;
    const int gid = lane >> 2;
    const int tig = lane & 3;
    const int mBase = blockIdx.y * 128;
    const int nBase = blockIdx.x * 128;

    float acc[2][8][4];
#pragma unroll
    for (int mt = 0; mt < 2; mt++)
#pragma unroll
        for (int nt = 0; nt < 8; nt++)
#pragma unroll
            for (int i = 0; i < 4; i++) acc[mt][nt][i] = 0.f;

    const int T = K >> 5;

    gemm_load_tiles(A, W, asm0, bsm0, K, N, mBase, nBase, 0, tid);
    CP_COMMIT();

    for (int t = 0; t < T; t++) {
        const int buf = t & 1;
        if (t + 1 < T) {
            gemm_load_tiles(A, W, asm0 + (buf ^ 1) * ASZ, bsm0 + (buf ^ 1) * BSZ,
                            K, N, mBase, nBase, (t + 1) * 32, tid);
            CP_COMMIT();
            CP_WAIT(1);
        } else {
            CP_WAIT(0);
        }
        __syncthreads();

        const float* as = asm0 + buf * ASZ;
        const float* bs = bsm0 + buf * BSZ;

#pragma unroll
        for (int ks = 0; ks < 4; ks++) {
            const int kk = ks * 8;
            uint32_t af[2][4];
#pragma unroll
            for (int mt = 0; mt < 2; mt++) {
                const float* ap = as + (wm * 32 + mt * 16 + gid) * 36 + kk + tig;
                af[mt][0] = f2tf32(ap[0]);
                af[mt][1] = f2tf32(ap[8 * 36]);
                af[mt][2] = f2tf32(ap[4]);
                af[mt][3] = f2tf32(ap[8 * 36 + 4]);
            }
#pragma unroll
            for (int nt = 0; nt < 8; nt++) {
                const float* bp = bs + (kk + tig) * 132 + wn * 64 + nt * 8 + gid;
                uint32_t b0 = f2tf32(bp[0]);
                uint32_t b1 = f2tf32(bp[4 * 132]);
                mma_tf32(acc[0][nt], af[0], b0, b1);
                mma_tf32(acc[1][nt], af[1], b0, b1);
            }
        }
        __syncthreads();
    }

#pragma unroll
    for (int mt = 0; mt < 2; mt++) {
#pragma unroll
        for (int nt = 0; nt < 8; nt++) {
            const int r = mBase + wm * 32 + mt * 16 + gid;
            const int c = nBase + wn * 64 + nt * 8 + 2 * tig;
            float2 v0 = make_float2(acc[mt][nt][0], acc[mt][nt][1]);
            float2 v1 = make_float2(acc[mt][nt][2], acc[mt][nt][3]);
            *(float2*)(C + (size_t)r * ldc + c) = v0;
            *(float2*)(C + (size_t)(r + 8) * ldc + c) = v1;
        }
    }
}

// ---------------------------------------------------------------------------
// RoPE in place on Q (heads 0..31) and K (heads 32..39) sections of g_qkv.
// ---------------------------------------------------------------------------
__global__ void rope_kernel(const int* __restrict__ pos_ids)
{
    const int bs = blockIdx.x;
    const float p = (float)pos_ids[bs];
    float* base = g_qkv + (size_t)bs * QKVW;

    const float NEG_L2T_OVER_32 = -0.41524101186092029f;   // -log2(10000)/32

    for (int idx = threadIdx.x; idx < (NH_ + NKV_) * 32; idx += blockDim.x) {
        const int head = idx >> 5;
        const int i = idx & 31;
        const float inv = exp2f((float)i * NEG_L2T_OVER_32);
        const float ang = p * inv;
        float sv, cv;
        sincosf(ang, &sv, &cv);
        float* hp = base + head * DH_;
        const float x1 = hp[i];
        const float x2 = hp[i + 32];
        hp[i]      = x1 * cv - x2 * sv;
        hp[i + 32] = x2 * cv + x1 * sv;
    }
}

// ---------------------------------------------------------------------------
// Tensor-core flash attention (tf32 mma): grid (S/128, NH, B), 256 threads.
// Warp w owns query rows qBase + 16w .. +15. KV tiles of 64 keys.
// Smem (floats, row stride 68 -> conflict-free fragment addressing):
//   Qs[128][68] row-major, Ks[64][68] (= B operand [n=key][k=dh]),
//   Vts[64][68] = V^T (= B operand [n=dh][k=key]), Ps[128][68] (per-warp P).
// ---------------------------------------------------------------------------
#define FA_PAD 68
#define FQ (128 * FA_PAD)
#define FK (64 * FA_PAD)
#define FV (64 * FA_PAD)
#define FP (128 * FA_PAD)
#define FA_SMEM ((FQ + FK + FV + FP) * 4)

__global__ __launch_bounds__(256, 2) void flash_attn_tc()
{
    extern __shared__ float smf[];
    float* Qs  = smf;
    float* Ks  = smf + FQ;
    float* Vts = Ks + FK;
    float* Ps  = Vts + FV;

    const int qt = blockIdx.x, h = blockIdx.y, b = blockIdx.z;
    const int kh = h >> 2;
    const int tid  = threadIdx.x;
    const int lane = tid & 31;
    const int w    = tid >> 5;
    const int gid  = lane >> 2;     // 0..7
    const int tig  = lane & 3;      // 0..3
    const int qBase = qt * 128;

    const float* Qg = g_qkv + (size_t)b * S_ * QKVW + h * 64;
    const float* Kg = g_qkv + (size_t)b * S_ * QKVW + 2048 + kh * 64;
    const float* Vg = g_qkv + (size_t)b * S_ * QKVW + 2560 + kh * 64;

    // Async-load Q tile (128 x 64)
#pragma unroll
    for (int i = 0; i < 8; i++) {
        int idx = tid + i * 256;
        int r = idx >> 4, c4 = (idx & 15) * 4;
        cp_async16(Qs + r * FA_PAD + c4, Qg + (size_t)(qBase + r) * QKVW + c4);
    }
    CP_COMMIT();

    float o[8][4];
#pragma unroll
    for (int df = 0; df < 8; df++)
#pragma unroll
        for (int i = 0; i < 4; i++) o[df][i] = 0.f;
    float m_run[2] = {-INFINITY, -INFINITY};
    float l_run[2] = {0.f, 0.f};

    const int nTiles = 2 * qt + 2;
    const int rowMaxW = qBase + w * 16 + 15;   // max query row of this warp

    for (int jt = 0; jt < nTiles; jt++) {
        __syncthreads();   // previous tile's K/V fully consumed

        // Load K tile (64 keys x 64 dh) via cp.async
#pragma unroll
        for (int i = 0; i < 4; i++) {
            int idx = tid + i * 256;
            int r = idx >> 4, c4 = (idx & 15) * 4;
            cp_async16(Ks + r * FA_PAD + c4, Kg + (size_t)(jt * 64 + r) * QKVW + c4);
        }
        CP_COMMIT();
        // Load V tile transposed: Vts[d][key]
#pragma unroll
        for (int i = 0; i < 4; i++) {
            int idx = tid + i * 256;
            int r = idx >> 4, d4 = (idx & 15) * 4;
            float4 v = *(const float4*)(Vg + (size_t)(jt * 64 + r) * QKVW + d4);
            Vts[(d4 + 0) * FA_PAD + r] = v.x;
            Vts[(d4 + 1) * FA_PAD + r] = v.y;
            Vts[(d4 + 2) * FA_PAD + r] = v.z;
            Vts[(d4 + 3) * FA_PAD + r] = v.w;
        }
        CP_WAIT(0);
        __syncthreads();

        if (jt * 64 <= rowMaxW) {    // tile not fully masked for this warp
            // ---- S = Q @ K^T (warp rows 16w..16w+15, 64 keys) ----
            float s[8][4];
#pragma unroll
            for (int nf = 0; nf < 8; nf++)
#pragma unroll
                for (int i = 0; i < 4; i++) s[nf][i] = 0.f;

#pragma unroll
            for (int ks = 0; ks < 8; ks++) {
                const float* ap = Qs + (w * 16 + gid) * FA_PAD + ks * 8 + tig;
                uint32_t af[4];
                af[0] = f2tf32(ap[0]);
                af[1] = f2tf32(ap[8 * FA_PAD]);
                af[2] = f2tf32(ap[4]);
                af[3] = f2tf32(ap[8 * FA_PAD + 4]);
#pragma unroll
                for (int nf = 0; nf < 8; nf++) {
                    const float* bp = Ks + (nf * 8 + gid) * FA_PAD + ks * 8 + tig;
                    uint32_t b0 = f2tf32(bp[0]);
                    uint32_t b1 = f2tf32(bp[4]);
                    mma_tf32(s[nf], af, b0, b1);
                }
            }

            // ---- scale + causal mask ----
            const int r0 = qBase + w * 16 + gid;
            const int r1 = r0 + 8;
            const int cb = jt * 64;
#pragma unroll
            for (int nf = 0; nf < 8; nf++) {
                int c0 = cb + nf * 8 + 2 * tig;
                s[nf][0] = (c0     > r0) ? -1e30f : s[nf][0] * 0.125f;
                s[nf][1] = (c0 + 1 > r0) ? -1e30f : s[nf][1] * 0.125f;
                s[nf][2] = (c0     > r1) ? -1e30f : s[nf][2] * 0.125f;
                s[nf][3] = (c0 + 1 > r1) ? -1e30f : s[nf][3] * 0.125f;
            }

            // ---- online softmax (rows gid and gid+8; quad reductions) ----
            float mx0 = -INFINITY, mx1 = -INFINITY;
#pragma unroll
            for (int nf = 0; nf < 8; nf++) {
                mx0 = fmaxf(mx0, fmaxf(s[nf][0], s[nf][1]));
                mx1 = fmaxf(mx1, fmaxf(s[nf][2], s[nf][3]));
            }
#pragma unroll
            for (int off = 1; off < 4; off <<= 1) {
                mx0 = fmaxf(mx0, __shfl_xor_sync(0xffffffffu, mx0, off));
                mx1 = fmaxf(mx1, __shfl_xor_sync(0xffffffffu, mx1, off));
            }
            const float mn0 = fmaxf(m_run[0], mx0);
            const float mn1 = fmaxf(m_run[1], mx1);
            const float al0 = expf(m_run[0] - mn0);
            const float al1 = expf(m_run[1] - mn1);
            m_run[0] = mn0; m_run[1] = mn1;

            float rs0 = 0.f, rs1 = 0.f;
#pragma unroll
            for (int nf = 0; nf < 8; nf++) {
                float p0 = expf(s[nf][0] - mn0);
                float p1 = expf(s[nf][1] - mn0);
                float p2 = expf(s[nf][2] - mn1);
                float p3 = expf(s[nf][3] - mn1);
                s[nf][0] = p0; s[nf][1] = p1; s[nf][2] = p2; s[nf][3] = p3;
                rs0 += p0 + p1;
                rs1 += p2 + p3;
            }
#pragma unroll
            for (int off = 1; off < 4; off <<= 1) {
                rs0 += __shfl_xor_sync(0xffffffffu, rs0, off);
                rs1 += __shfl_xor_sync(0xffffffffu, rs1, off);
            }
            l_run[0] = l_run[0] * al0 + rs0;
            l_run[1] = l_run[1] * al1 + rs1;
#pragma unroll
            for (int df = 0; df < 8; df++) {
                o[df][0] *= al0; o[df][1] *= al0;
                o[df][2] *= al1; o[df][3] *= al1;
            }

            // ---- write P (this warp's rows only) ----
            float* pp0 = Ps + (w * 16 + gid) * FA_PAD;
            float* pp1 = pp0 + 8 * FA_PAD;
#pragma unroll
            for (int nf = 0; nf < 8; nf++) {
                *(float2*)(pp0 + nf * 8 + 2 * tig) = make_float2(s[nf][0], s[nf][1]);
                *(float2*)(pp1 + nf * 8 + 2 * tig) = make_float2(s[nf][2], s[nf][3]);
            }
            __syncwarp();

            // ---- O += P @ V  (B operand = Vts) ----
#pragma unroll
            for (int ks = 0; ks < 8; ks++) {
                const float* ap = Ps + (w * 16 + gid) * FA_PAD + ks * 8 + tig;
                uint32_t af[4];
                af[0] = f2tf32(ap[0]);
                af[1] = f2tf32(ap[8 * FA_PAD]);
                af[2] = f2tf32(ap[4]);
                af[3] = f2tf32(ap[8 * FA_PAD + 4]);
#pragma unroll
                for (int df = 0; df < 8; df++) {
                    const float* bp = Vts + (df * 8 + gid) * FA_PAD + ks * 8 + tig;
                    uint32_t b0 = f2tf32(bp[0]);
                    uint32_t b1 = f2tf32(bp[4]);
                    mma_tf32(o[df], af, b0, b1);
                }
            }
        }
    }

    // ---- epilogue: normalize, store to g_attn [B,S,NH*DH] ----
    const float il0 = 1.0f / l_run[0];
    const float il1 = 1.0f / l_run[1];
    const int r0 = qBase + w * 16 + gid;
    float* Og0 = g_attn + ((size_t)b * S_ + r0) * (NH_ * DH_) + h * 64;
    float* Og1 = Og0 + (size_t)8 * (NH_ * DH_);
#pragma unroll
    for (int df = 0; df < 8; df++) {
        *(float2*)(Og0 + df * 8 + 2 * tig) = make_float2(o[df][0] * il0, o[df][1] * il0);
        *(float2*)(Og1 + df * 8 + 2 * tig) = make_float2(o[df][2] * il1, o[df][3] * il1);
    }
}

// ---------------------------------------------------------------------------
// Launch
// ---------------------------------------------------------------------------
extern "C" void kernel_launch(void* const* d_in, const int* in_sizes, int n_in,
                              void* d_out, int out_size)
{
    const float* X   = (const float*)d_in[0];
    const int*   pos = (const int*)d_in[1];
    const float* Wq  = (const float*)d_in[2];
    const float* Wk  = (const float*)d_in[3];
    const float* Wv  = (const float*)d_in[4];
    const float* Wo  = (const float*)d_in[5];
    float* out = (float*)d_out;

    float* qkv_p = nullptr;
    float* attn_p = nullptr;
    cudaGetSymbolAddress((void**)&qkv_p, g_qkv);
    cudaGetSymbolAddress((void**)&attn_p, g_attn);

    cudaFuncSetAttribute(gemm_tf32, cudaFuncAttributeMaxDynamicSharedMemorySize, GEMM_SMEM);
    cudaFuncSetAttribute(flash_attn_tc, cudaFuncAttributeMaxDynamicSharedMemorySize, FA_SMEM);

    // QKV projections into the packed buffer (ldc = 3072)
    gemm_tf32<<<dim3(16, 32), 256, GEMM_SMEM>>>(X, Wq, qkv_p,        2048, 2048, QKVW);
    gemm_tf32<<<dim3(4, 32),  256, GEMM_SMEM>>>(X, Wk, qkv_p + 2048, 2048, 512,  QKVW);
    gemm_tf32<<<dim3(4, 32),  256, GEMM_SMEM>>>(X, Wv, qkv_p + 2560, 2048, 512,  QKVW);

    // RoPE on Q and K in place
    rope_kernel<<<B_ * S_, 256>>>(pos);

    // Tensor-core flash attention
    flash_attn_tc<<<dim3(S_ / 128, NH_, B_), 256, FA_SMEM>>>();

    // Output projection
    gemm_tf32<<<dim3(16, 32), 256, GEMM_SMEM>>>(attn_p, Wo, out, 2048, 2048, 2048);
}

// round 8
// speedup vs baseline: 3.0245x; 1.0534x over previous
#include <cuda_runtime.h>
#include <math.h>
#include <stdint.h>

// Problem constants
#define B_ 2
#define S_ 2048
#define H_ 2048
#define NH_ 32
#define NKV_ 8
#define DH_ 64
#define NREP_ 4
#define QKVW 3072   // NH*DH + 2*NKV*DH

// Scratch (device globals: no allocation allowed)
__device__ float g_qkv[(size_t)B_ * S_ * QKVW];          // Q | K | V per token, RoPE applied in place (tf32-rounded)
__device__ float g_attn[(size_t)B_ * S_ * NH_ * DH_];    // attention output [B,S,NH*DH] (tf32-rounded)
__device__ float g_xr[(size_t)B_ * S_ * H_];             // X rounded to tf32
__device__ float g_w[(size_t)(QKVW + H_) * H_];          // rows: [Wq|Wk|Wv] packed [2048][3072], then Wo [2048][2048]

// ---------------------------------------------------------------------------
// Helpers
// ---------------------------------------------------------------------------
__device__ __forceinline__ void cp_async16(void* smem, const float* gmem) {
    uint32_t s = (uint32_t)__cvta_generic_to_shared(smem);
    asm volatile("cp.async.cg.shared.global [%0], [%1], 16;\n" :: "r"(s), "l"(gmem));
}
#define CP_COMMIT() asm volatile("cp.async.commit_group;\n" ::: "memory")
#define CP_WAIT(n)  asm volatile("cp.async.wait_group %0;\n" :: "n"(n) : "memory")

__device__ __forceinline__ uint32_t f2tf32(float x) {
    uint32_t r;
    asm("cvt.rna.tf32.f32 %0, %1;" : "=r"(r) : "f"(x));
    return r;
}
__device__ __forceinline__ float roundtf(float x) { return __uint_as_float(f2tf32(x)); }

__device__ __forceinline__ void mma_tf32(float* c, const uint32_t* a, uint32_t b0, uint32_t b1) {
    asm volatile(
        "mma.sync.aligned.m16n8k8.row.col.f32.tf32.tf32.f32 "
        "{%0,%1,%2,%3}, {%4,%5,%6,%7}, {%8,%9}, {%0,%1,%2,%3};"
        : "+f"(c[0]), "+f"(c[1]), "+f"(c[2]), "+f"(c[3])
        : "r"(a[0]), "r"(a[1]), "r"(a[2]), "r"(a[3]), "r"(b0), "r"(b1));
}

// ---------------------------------------------------------------------------
// Prep kernels: all tf32 rounding happens HERE, never in mma inner loops.
// ---------------------------------------------------------------------------
__global__ void round_x(const float4* __restrict__ in, float4* __restrict__ out)
{
    int i = blockIdx.x * blockDim.x + threadIdx.x;
    float4 v = in[i];
    v.x = roundtf(v.x); v.y = roundtf(v.y); v.z = roundtf(v.z); v.w = roundtf(v.w);
    out[i] = v;
}

// Pack + round [Wq|Wk|Wv] row-wise into g_w[0 .. 2048*3072). grid.x = 2048 rows.
__global__ void pack_qkv_w(const float4* __restrict__ Wq, const float4* __restrict__ Wk,
                           const float4* __restrict__ Wv, float4* __restrict__ out)
{
    const int k = blockIdx.x;                      // row 0..2047
    float4* orow = out + (size_t)k * (QKVW / 4);   // 768 float4s
    for (int c = threadIdx.x; c < QKVW / 4; c += blockDim.x) {
        float4 v;
        if (c < 512)       v = Wq[(size_t)k * 512 + c];
        else if (c < 640)  v = Wk[(size_t)k * 128 + (c - 512)];
        else               v = Wv[(size_t)k * 128 + (c - 640)];
        v.x = roundtf(v.x); v.y = roundtf(v.y); v.z = roundtf(v.z); v.w = roundtf(v.w);
        orow[c] = v;
    }
}

// ---------------------------------------------------------------------------
// tf32 tensor-core GEMM: C[M,N] = A[M,K] @ W[K,N]. Inputs PRE-ROUNDED to tf32
// (raw bits feed mma). BM=BN=128, BK=32, 256 threads, cp.async double buffer.
// ---------------------------------------------------------------------------
#define ASZ (128 * 36)
#define BSZ (32 * 132)
#define GEMM_SMEM ((2 * ASZ + 2 * BSZ) * 4)

__device__ __forceinline__ void gemm_load_tiles(
    const float* __restrict__ A, const float* __restrict__ W,
    float* as, float* bs, int K, int N, int mBase, int nBase, int k0, int tid)
{
#pragma unroll
    for (int i = 0; i < 4; i++) {                    // A tile: 128 x 32
        int idx = tid + i * 256;
        int r = idx >> 3, c4 = (idx & 7) * 4;
        cp_async16(as + r * 36 + c4, A + (size_t)(mBase + r) * K + k0 + c4);
    }
#pragma unroll
    for (int i = 0; i < 4; i++) {                    // B tile: 32 x 128
        int idx = tid + i * 256;
        int r = idx >> 5, n4 = (idx & 31) * 4;
        cp_async16(bs + r * 132 + n4, W + (size_t)(k0 + r) * N + nBase + n4);
    }
}

__global__ __launch_bounds__(256) void gemm_tf32(
    const float* __restrict__ A, const float* __restrict__ W,
    float* __restrict__ C, int K, int N, int ldc)
{
    extern __shared__ float sm[];
    float* asm0 = sm;
    float* bsm0 = sm + 2 * ASZ;

    const int tid = threadIdx.x;
    const int lane = tid & 31;
    const int wid = tid >> 5;
    const int wm = wid & 3;
    const int wn = wid >> 2;
    const int gid = lane >> 2;
    const int tig = lane & 3;
    const int mBase = blockIdx.y * 128;
    const int nBase = blockIdx.x * 128;

    float acc[2][8][4];
#pragma unroll
    for (int mt = 0; mt < 2; mt++)
#pragma unroll
        for (int nt = 0; nt < 8; nt++)
#pragma unroll
            for (int i = 0; i < 4; i++) acc[mt][nt][i] = 0.f;

    const int T = K >> 5;

    gemm_load_tiles(A, W, asm0, bsm0, K, N, mBase, nBase, 0, tid);
    CP_COMMIT();

    for (int t = 0; t < T; t++) {
        const int buf = t & 1;
        if (t + 1 < T) {
            gemm_load_tiles(A, W, asm0 + (buf ^ 1) * ASZ, bsm0 + (buf ^ 1) * BSZ,
                            K, N, mBase, nBase, (t + 1) * 32, tid);
            CP_COMMIT();
            CP_WAIT(1);
        } else {
            CP_WAIT(0);
        }
        __syncthreads();

        const uint32_t* as = (const uint32_t*)(asm0 + buf * ASZ);
        const uint32_t* bs = (const uint32_t*)(bsm0 + buf * BSZ);

#pragma unroll
        for (int ks = 0; ks < 4; ks++) {
            const int kk = ks * 8;
            uint32_t af[2][4];
#pragma unroll
            for (int mt = 0; mt < 2; mt++) {
                const uint32_t* ap = as + (wm * 32 + mt * 16 + gid) * 36 + kk + tig;
                af[mt][0] = ap[0];
                af[mt][1] = ap[8 * 36];
                af[mt][2] = ap[4];
                af[mt][3] = ap[8 * 36 + 4];
            }
#pragma unroll
            for (int nt = 0; nt < 8; nt++) {
                const uint32_t* bp = bs + (kk + tig) * 132 + wn * 64 + nt * 8 + gid;
                uint32_t b0 = bp[0];
                uint32_t b1 = bp[4 * 132];
                mma_tf32(acc[0][nt], af[0], b0, b1);
                mma_tf32(acc[1][nt], af[1], b0, b1);
            }
        }
        __syncthreads();
    }

#pragma unroll
    for (int mt = 0; mt < 2; mt++) {
#pragma unroll
        for (int nt = 0; nt < 8; nt++) {
            const int r = mBase + wm * 32 + mt * 16 + gid;
            const int c = nBase + wn * 64 + nt * 8 + 2 * tig;
            float2 v0 = make_float2(acc[mt][nt][0], acc[mt][nt][1]);
            float2 v1 = make_float2(acc[mt][nt][2], acc[mt][nt][3]);
            *(float2*)(C + (size_t)r * ldc + c) = v0;
            *(float2*)(C + (size_t)(r + 8) * ldc + c) = v1;
        }
    }
}

// ---------------------------------------------------------------------------
// RoPE in place on Q (heads 0..31) and K (heads 32..39); outputs tf32-rounded
// so attention fragments can be fed as raw bits. V left as-is (rounded at
// the flash transpose-store).
// ---------------------------------------------------------------------------
__global__ void rope_kernel(const int* __restrict__ pos_ids)
{
    const int bs = blockIdx.x;
    const float p = (float)pos_ids[bs];
    float* base = g_qkv + (size_t)bs * QKVW;

    const float NEG_L2T_OVER_32 = -0.41524101186092029f;   // -log2(10000)/32

    for (int idx = threadIdx.x; idx < (NH_ + NKV_) * 32; idx += blockDim.x) {
        const int head = idx >> 5;
        const int i = idx & 31;
        const float inv = exp2f((float)i * NEG_L2T_OVER_32);
        const float ang = p * inv;
        float sv, cv;
        sincosf(ang, &sv, &cv);
        float* hp = base + head * DH_;
        const float x1 = hp[i];
        const float x2 = hp[i + 32];
        hp[i]      = roundtf(x1 * cv - x2 * sv);
        hp[i + 32] = roundtf(x2 * cv + x1 * sv);
    }
}

// ---------------------------------------------------------------------------
// Tensor-core flash attention (tf32 mma.sync): grid (S/128, NH, B), 256 thr.
// All mma operands pre-rounded (Q/K by rope; V at transpose-store; P at smem
// write) -> inner loops are pure LDS+MMA. Output tf32-rounded for the Wo GEMM.
// ---------------------------------------------------------------------------
#define FA_PAD 68
#define FQ (128 * FA_PAD)
#define FK (64 * FA_PAD)
#define FV (64 * FA_PAD)
#define FP (128 * FA_PAD)
#define FA_SMEM ((FQ + FK + FV + FP) * 4)

__global__ __launch_bounds__(256, 2) void flash_attn_tc()
{
    extern __shared__ float smf[];
    float* Qs  = smf;
    float* Ks  = smf + FQ;
    float* Vts = Ks + FK;
    float* Ps  = Vts + FV;

    const int qt = blockIdx.x, h = blockIdx.y, b = blockIdx.z;
    const int kh = h >> 2;
    const int tid  = threadIdx.x;
    const int lane = tid & 31;
    const int w    = tid >> 5;
    const int gid  = lane >> 2;
    const int tig  = lane & 3;
    const int qBase = qt * 128;

    const float* Qg = g_qkv + (size_t)b * S_ * QKVW + h * 64;
    const float* Kg = g_qkv + (size_t)b * S_ * QKVW + 2048 + kh * 64;
    const float* Vg = g_qkv + (size_t)b * S_ * QKVW + 2560 + kh * 64;

#pragma unroll
    for (int i = 0; i < 8; i++) {
        int idx = tid + i * 256;
        int r = idx >> 4, c4 = (idx & 15) * 4;
        cp_async16(Qs + r * FA_PAD + c4, Qg + (size_t)(qBase + r) * QKVW + c4);
    }
    CP_COMMIT();

    float o[8][4];
#pragma unroll
    for (int df = 0; df < 8; df++)
#pragma unroll
        for (int i = 0; i < 4; i++) o[df][i] = 0.f;
    float m_run[2] = {-INFINITY, -INFINITY};
    float l_run[2] = {0.f, 0.f};

    const int nTiles = 2 * qt + 2;
    const int rowMaxW = qBase + w * 16 + 15;

    for (int jt = 0; jt < nTiles; jt++) {
        __syncthreads();

#pragma unroll
        for (int i = 0; i < 4; i++) {
            int idx = tid + i * 256;
            int r = idx >> 4, c4 = (idx & 15) * 4;
            cp_async16(Ks + r * FA_PAD + c4, Kg + (size_t)(jt * 64 + r) * QKVW + c4);
        }
        CP_COMMIT();
        // V tile transposed + tf32-rounded: Vts[d][key]
#pragma unroll
        for (int i = 0; i < 4; i++) {
            int idx = tid + i * 256;
            int r = idx >> 4, d4 = (idx & 15) * 4;
            float4 v = *(const float4*)(Vg + (size_t)(jt * 64 + r) * QKVW + d4);
            Vts[(d4 + 0) * FA_PAD + r] = roundtf(v.x);
            Vts[(d4 + 1) * FA_PAD + r] = roundtf(v.y);
            Vts[(d4 + 2) * FA_PAD + r] = roundtf(v.z);
            Vts[(d4 + 3) * FA_PAD + r] = roundtf(v.w);
        }
        CP_WAIT(0);
        __syncthreads();

        if (jt * 64 <= rowMaxW) {
            // ---- S = Q @ K^T (raw-bit tf32 fragments) ----
            float s[8][4];
#pragma unroll
            for (int nf = 0; nf < 8; nf++)
#pragma unroll
                for (int i = 0; i < 4; i++) s[nf][i] = 0.f;

            const uint32_t* Qu = (const uint32_t*)Qs;
            const uint32_t* Ku = (const uint32_t*)Ks;
#pragma unroll
            for (int ks = 0; ks < 8; ks++) {
                const uint32_t* ap = Qu + (w * 16 + gid) * FA_PAD + ks * 8 + tig;
                uint32_t af[4];
                af[0] = ap[0];
                af[1] = ap[8 * FA_PAD];
                af[2] = ap[4];
                af[3] = ap[8 * FA_PAD + 4];
#pragma unroll
                for (int nf = 0; nf < 8; nf++) {
                    const uint32_t* bp = Ku + (nf * 8 + gid) * FA_PAD + ks * 8 + tig;
                    mma_tf32(s[nf], af, bp[0], bp[4]);
                }
            }

            const int r0 = qBase + w * 16 + gid;
            const int r1 = r0 + 8;
            const int cb = jt * 64;
#pragma unroll
            for (int nf = 0; nf < 8; nf++) {
                int c0 = cb + nf * 8 + 2 * tig;
                s[nf][0] = (c0     > r0) ? -1e30f : s[nf][0] * 0.125f;
                s[nf][1] = (c0 + 1 > r0) ? -1e30f : s[nf][1] * 0.125f;
                s[nf][2] = (c0     > r1) ? -1e30f : s[nf][2] * 0.125f;
                s[nf][3] = (c0 + 1 > r1) ? -1e30f : s[nf][3] * 0.125f;
            }

            float mx0 = -INFINITY, mx1 = -INFINITY;
#pragma unroll
            for (int nf = 0; nf < 8; nf++) {
                mx0 = fmaxf(mx0, fmaxf(s[nf][0], s[nf][1]));
                mx1 = fmaxf(mx1, fmaxf(s[nf][2], s[nf][3]));
            }
#pragma unroll
            for (int off = 1; off < 4; off <<= 1) {
                mx0 = fmaxf(mx0, __shfl_xor_sync(0xffffffffu, mx0, off));
                mx1 = fmaxf(mx1, __shfl_xor_sync(0xffffffffu, mx1, off));
            }
            const float mn0 = fmaxf(m_run[0], mx0);
            const float mn1 = fmaxf(m_run[1], mx1);
            const float al0 = expf(m_run[0] - mn0);
            const float al1 = expf(m_run[1] - mn1);
            m_run[0] = mn0; m_run[1] = mn1;

            float rs0 = 0.f, rs1 = 0.f;
#pragma unroll
            for (int nf = 0; nf < 8; nf++) {
                float p0 = expf(s[nf][0] - mn0);
                float p1 = expf(s[nf][1] - mn0);
                float p2 = expf(s[nf][2] - mn1);
                float p3 = expf(s[nf][3] - mn1);
                s[nf][0] = p0; s[nf][1] = p1; s[nf][2] = p2; s[nf][3] = p3;
                rs0 += p0 + p1;
                rs1 += p2 + p3;
            }
#pragma unroll
            for (int off = 1; off < 4; off <<= 1) {
                rs0 += __shfl_xor_sync(0xffffffffu, rs0, off);
                rs1 += __shfl_xor_sync(0xffffffffu, rs1, off);
            }
            l_run[0] = l_run[0] * al0 + rs0;
            l_run[1] = l_run[1] * al1 + rs1;
#pragma unroll
            for (int df = 0; df < 8; df++) {
                o[df][0] *= al0; o[df][1] *= al0;
                o[df][2] *= al1; o[df][3] *= al1;
            }

            // ---- write P (tf32-rounded; this warp's rows only) ----
            float* pp0 = Ps + (w * 16 + gid) * FA_PAD;
            float* pp1 = pp0 + 8 * FA_PAD;
#pragma unroll
            for (int nf = 0; nf < 8; nf++) {
                *(float2*)(pp0 + nf * 8 + 2 * tig) =
                    make_float2(roundtf(s[nf][0]), roundtf(s[nf][1]));
                *(float2*)(pp1 + nf * 8 + 2 * tig) =
                    make_float2(roundtf(s[nf][2]), roundtf(s[nf][3]));
            }
            __syncwarp();

            // ---- O += P @ V (raw-bit fragments) ----
            const uint32_t* Pu = (const uint32_t*)Ps;
            const uint32_t* Vu = (const uint32_t*)Vts;
#pragma unroll
            for (int ks = 0; ks < 8; ks++) {
                const uint32_t* ap = Pu + (w * 16 + gid) * FA_PAD + ks * 8 + tig;
                uint32_t af[4];
                af[0] = ap[0];
                af[1] = ap[8 * FA_PAD];
                af[2] = ap[4];
                af[3] = ap[8 * FA_PAD + 4];
#pragma unroll
                for (int df = 0; df < 8; df++) {
                    const uint32_t* bp = Vu + (df * 8 + gid) * FA_PAD + ks * 8 + tig;
                    mma_tf32(o[df], af, bp[0], bp[4]);
                }
            }
        }
    }

    // Epilogue: normalize, round to tf32 (feeds the Wo GEMM), store.
    const float il0 = 1.0f / l_run[0];
    const float il1 = 1.0f / l_run[1];
    const int r0 = qBase + w * 16 + gid;
    float* Og0 = g_attn + ((size_t)b * S_ + r0) * (NH_ * DH_) + h * 64;
    float* Og1 = Og0 + (size_t)8 * (NH_ * DH_);
#pragma unroll
    for (int df = 0; df < 8; df++) {
        *(float2*)(Og0 + df * 8 + 2 * tig) =
            make_float2(roundtf(o[df][0] * il0), roundtf(o[df][1] * il0));
        *(float2*)(Og1 + df * 8 + 2 * tig) =
            make_float2(roundtf(o[df][2] * il1), roundtf(o[df][3] * il1));
    }
}

// ---------------------------------------------------------------------------
// Launch
// ---------------------------------------------------------------------------
extern "C" void kernel_launch(void* const* d_in, const int* in_sizes, int n_in,
                              void* d_out, int out_size)
{
    const float* X   = (const float*)d_in[0];
    const int*   pos = (const int*)d_in[1];
    const float* Wq  = (const float*)d_in[2];
    const float* Wk  = (const float*)d_in[3];
    const float* Wv  = (const float*)d_in[4];
    const float* Wo  = (const float*)d_in[5];
    float* out = (float*)d_out;

    float *qkv_p, *attn_p, *xr_p, *w_p;
    cudaGetSymbolAddress((void**)&qkv_p, g_qkv);
    cudaGetSymbolAddress((void**)&attn_p, g_attn);
    cudaGetSymbolAddress((void**)&xr_p, g_xr);
    cudaGetSymbolAddress((void**)&w_p, g_w);

    cudaFuncSetAttribute(gemm_tf32, cudaFuncAttributeMaxDynamicSharedMemorySize, GEMM_SMEM);
    cudaFuncSetAttribute(flash_attn_tc, cudaFuncAttributeMaxDynamicSharedMemorySize, FA_SMEM);

    // Pre-round inputs once (removes all cvt from mma inner loops)
    round_x<<<(B_ * S_ * H_ / 4) / 256, 256>>>((const float4*)X, (float4*)xr_p);
    pack_qkv_w<<<2048, 256>>>((const float4*)Wq, (const float4*)Wk,
                              (const float4*)Wv, (float4*)w_p);
    round_x<<<(H_ * H_ / 4) / 256, 256>>>((const float4*)Wo,
                                          (float4*)(w_p + (size_t)2048 * QKVW));

    // Fused QKV projection: qkv[4096,3072] = Xr @ [Wq|Wk|Wv]
    gemm_tf32<<<dim3(24, 32), 256, GEMM_SMEM>>>(xr_p, w_p, qkv_p, 2048, QKVW, QKVW);

    // RoPE on Q and K in place (tf32-rounded outputs)
    rope_kernel<<<B_ * S_, 256>>>(pos);

    // Tensor-core flash attention
    flash_attn_tc<<<dim3(S_ / 128, NH_, B_), 256, FA_SMEM>>>();

    // Output projection: out = attn @ Wo
    gemm_tf32<<<dim3(16, 32), 256, GEMM_SMEM>>>(attn_p, w_p + (size_t)2048 * QKVW,
                                                out, 2048, 2048, 2048);
}

// round 11
// speedup vs baseline: 3.2800x; 1.0845x over previous
#include <cuda_runtime.h>
#include <math.h>
#include <stdint.h>

// Problem constants
#define B_ 2
#define S_ 2048
#define H_ 2048
#define NH_ 32
#define NKV_ 8
#define DH_ 64
#define NREP_ 4
#define QKVW 3072   // NH*DH + 2*NKV*DH

// Scratch (device globals: no allocation allowed)
__device__ float g_qkv[(size_t)B_ * S_ * QKVW];          // Q | K | V per token, RoPE applied in place (tf32-rounded)
__device__ float g_attn[(size_t)B_ * S_ * NH_ * DH_];    // attention output [B,S,NH*DH] (tf32-rounded)
__device__ float g_xr[(size_t)B_ * S_ * H_];             // X rounded to tf32
__device__ float g_w[(size_t)(QKVW + H_) * H_];          // rows: [Wq|Wk|Wv] packed [2048][3072], then Wo [2048][2048]

// ---------------------------------------------------------------------------
// Helpers
// ---------------------------------------------------------------------------
__device__ __forceinline__ void cp_async16(void* smem, const float* gmem) {
    uint32_t s = (uint32_t)__cvta_generic_to_shared(smem);
    asm volatile("cp.async.cg.shared.global [%0], [%1], 16;\n" :: "r"(s), "l"(gmem));
}
#define CP_COMMIT() asm volatile("cp.async.commit_group;\n" ::: "memory")
#define CP_WAIT(n)  asm volatile("cp.async.wait_group %0;\n" :: "n"(n) : "memory")

__device__ __forceinline__ uint32_t f2tf32(float x) {
    uint32_t r;
    asm("cvt.rna.tf32.f32 %0, %1;" : "=r"(r) : "f"(x));
    return r;
}
__device__ __forceinline__ float roundtf(float x) { return __uint_as_float(f2tf32(x)); }

__device__ __forceinline__ void mma_tf32(float* c, const uint32_t* a, uint32_t b0, uint32_t b1) {
    asm volatile(
        "mma.sync.aligned.m16n8k8.row.col.f32.tf32.tf32.f32 "
        "{%0,%1,%2,%3}, {%4,%5,%6,%7}, {%8,%9}, {%0,%1,%2,%3};"
        : "+f"(c[0]), "+f"(c[1]), "+f"(c[2]), "+f"(c[3])
        : "r"(a[0]), "r"(a[1]), "r"(a[2]), "r"(a[3]), "r"(b0), "r"(b1));
}

// ---------------------------------------------------------------------------
// Prep kernels: all tf32 rounding happens HERE, never in mma inner loops.
// ---------------------------------------------------------------------------
__global__ void round_x(const float4* __restrict__ in, float4* __restrict__ out)
{
    int i = blockIdx.x * blockDim.x + threadIdx.x;
    float4 v = in[i];
    v.x = roundtf(v.x); v.y = roundtf(v.y); v.z = roundtf(v.z); v.w = roundtf(v.w);
    out[i] = v;
}

// Pack + round [Wq|Wk|Wv] row-wise into g_w[0 .. 2048*3072). grid.x = 2048 rows.
__global__ void pack_qkv_w(const float4* __restrict__ Wq, const float4* __restrict__ Wk,
                           const float4* __restrict__ Wv, float4* __restrict__ out)
{
    const int k = blockIdx.x;                      // row 0..2047
    float4* orow = out + (size_t)k * (QKVW / 4);   // 768 float4s
    for (int c = threadIdx.x; c < QKVW / 4; c += blockDim.x) {
        float4 v;
        if (c < 512)       v = Wq[(size_t)k * 512 + c];
        else if (c < 640)  v = Wk[(size_t)k * 128 + (c - 512)];
        else               v = Wv[(size_t)k * 128 + (c - 640)];
        v.x = roundtf(v.x); v.y = roundtf(v.y); v.z = roundtf(v.z); v.w = roundtf(v.w);
        orow[c] = v;
    }
}

// ---------------------------------------------------------------------------
// tf32 tensor-core GEMM: C[M,N] = A[M,K] @ W[K,N]. Inputs PRE-ROUNDED to tf32.
// BM=BN=128, BK=32. 128 threads = 4 warps, warp tile 64x64 (2x2 warp grid):
// per ks-step each warp does 32 LDS for 32 mmas (1.0 LDS/mma) and each B
// fragment feeds 4 mmas. B smem stride 136 floats -> fragment bank index
// (8*tig+gid)%32 all-distinct (conflict-free); A stride 36 as before.
// ---------------------------------------------------------------------------
#define ASZ (128 * 36)
#define BSTR 136
#define BSZ (32 * BSTR)
#define GEMM_SMEM ((2 * ASZ + 2 * BSZ) * 4)

__device__ __forceinline__ void gemm_load_tiles(
    const float* __restrict__ A, const float* __restrict__ W,
    float* as, float* bs, int K, int N, int mBase, int nBase, int k0, int tid)
{
#pragma unroll
    for (int i = 0; i < 8; i++) {                    // A tile: 128 x 32
        int idx = tid + i * 128;
        int r = idx >> 3, c4 = (idx & 7) * 4;
        cp_async16(as + r * 36 + c4, A + (size_t)(mBase + r) * K + k0 + c4);
    }
#pragma unroll
    for (int i = 0; i < 8; i++) {                    // B tile: 32 x 128
        int idx = tid + i * 128;
        int r = idx >> 5, n4 = (idx & 31) * 4;
        cp_async16(bs + r * BSTR + n4, W + (size_t)(k0 + r) * N + nBase + n4);
    }
}

__global__ __launch_bounds__(128, 2) void gemm_tf32(
    const float* __restrict__ A, const float* __restrict__ W,
    float* __restrict__ C, int K, int N, int ldc)
{
    extern __shared__ float sm[];
    float* asm0 = sm;
    float* bsm0 = sm + 2 * ASZ;

    const int tid = threadIdx.x;
    const int lane = tid & 31;
    const int wid = tid >> 5;
    const int wm = wid & 1;          // 2 warps on M: 64 rows each
    const int wn = wid >> 1;         // 2 warps on N: 64 cols each
    const int gid = lane >> 2;       // 0..7
    const int tig = lane & 3;        // 0..3
    const int mBase = blockIdx.y * 128;
    const int nBase = blockIdx.x * 128;

    float acc[4][8][4];
#pragma unroll
    for (int mt = 0; mt < 4; mt++)
#pragma unroll
        for (int nt = 0; nt < 8; nt++)
#pragma unroll
            for (int i = 0; i < 4; i++) acc[mt][nt][i] = 0.f;

    const int T = K >> 5;

    gemm_load_tiles(A, W, asm0, bsm0, K, N, mBase, nBase, 0, tid);
    CP_COMMIT();

    for (int t = 0; t < T; t++) {
        const int buf = t & 1;
        if (t + 1 < T) {
            gemm_load_tiles(A, W, asm0 + (buf ^ 1) * ASZ, bsm0 + (buf ^ 1) * BSZ,
                            K, N, mBase, nBase, (t + 1) * 32, tid);
            CP_COMMIT();
            CP_WAIT(1);
        } else {
            CP_WAIT(0);
        }
        __syncthreads();

        const uint32_t* as = (const uint32_t*)(asm0 + buf * ASZ);
        const uint32_t* bs = (const uint32_t*)(bsm0 + buf * BSZ);

#pragma unroll
        for (int ks = 0; ks < 4; ks++) {
            const int kk = ks * 8;
            uint32_t af[4][4];
#pragma unroll
            for (int mt = 0; mt < 4; mt++) {
                const uint32_t* ap = as + (wm * 64 + mt * 16 + gid) * 36 + kk + tig;
                af[mt][0] = ap[0];
                af[mt][1] = ap[8 * 36];
                af[mt][2] = ap[4];
                af[mt][3] = ap[8 * 36 + 4];
            }
#pragma unroll
            for (int nt = 0; nt < 8; nt++) {
                const uint32_t* bp = bs + (kk + tig) * BSTR + wn * 64 + nt * 8 + gid;
                uint32_t b0 = bp[0];
                uint32_t b1 = bp[4 * BSTR];
#pragma unroll
                for (int mt = 0; mt < 4; mt++)
                    mma_tf32(acc[mt][nt], af[mt], b0, b1);
            }
        }
        __syncthreads();
    }

#pragma unroll
    for (int mt = 0; mt < 4; mt++) {
#pragma unroll
        for (int nt = 0; nt < 8; nt++) {
            const int r = mBase + wm * 64 + mt * 16 + gid;
            const int c = nBase + wn * 64 + nt * 8 + 2 * tig;
            float2 v0 = make_float2(acc[mt][nt][0], acc[mt][nt][1]);
            float2 v1 = make_float2(acc[mt][nt][2], acc[mt][nt][3]);
            *(float2*)(C + (size_t)r * ldc + c) = v0;
            *(float2*)(C + (size_t)(r + 8) * ldc + c) = v1;
        }
    }
}

// ---------------------------------------------------------------------------
// RoPE in place on Q (heads 0..31) and K (heads 32..39); outputs tf32-rounded
// so attention fragments can be fed as raw bits.
// ---------------------------------------------------------------------------
__global__ void rope_kernel(const int* __restrict__ pos_ids)
{
    const int bs = blockIdx.x;
    const float p = (float)pos_ids[bs];
    float* base = g_qkv + (size_t)bs * QKVW;

    const float NEG_L2T_OVER_32 = -0.41524101186092029f;   // -log2(10000)/32

    for (int idx = threadIdx.x; idx < (NH_ + NKV_) * 32; idx += blockDim.x) {
        const int head = idx >> 5;
        const int i = idx & 31;
        const float inv = exp2f((float)i * NEG_L2T_OVER_32);
        const float ang = p * inv;
        float sv, cv;
        sincosf(ang, &sv, &cv);
        float* hp = base + head * DH_;
        const float x1 = hp[i];
        const float x2 = hp[i + 32];
        hp[i]      = roundtf(x1 * cv - x2 * sv);
        hp[i + 32] = roundtf(x2 * cv + x1 * sv);
    }
}

// ---------------------------------------------------------------------------
// Tensor-core flash attention (tf32 mma.sync): grid (S/128, NH, B), 256 thr.
// All mma operands pre-rounded; inner loops pure LDS+MMA.
// ---------------------------------------------------------------------------
#define FA_PAD 68
#define FQ (128 * FA_PAD)
#define FK (64 * FA_PAD)
#define FV (64 * FA_PAD)
#define FP (128 * FA_PAD)
#define FA_SMEM ((FQ + FK + FV + FP) * 4)

__global__ __launch_bounds__(256, 2) void flash_attn_tc()
{
    extern __shared__ float smf[];
    float* Qs  = smf;
    float* Ks  = smf + FQ;
    float* Vts = Ks + FK;
    float* Ps  = Vts + FV;

    const int qt = blockIdx.x, h = blockIdx.y, b = blockIdx.z;
    const int kh = h >> 2;
    const int tid  = threadIdx.x;
    const int lane = tid & 31;
    const int w    = tid >> 5;
    const int gid  = lane >> 2;
    const int tig  = lane & 3;
    const int qBase = qt * 128;

    const float* Qg = g_qkv + (size_t)b * S_ * QKVW + h * 64;
    const float* Kg = g_qkv + (size_t)b * S_ * QKVW + 2048 + kh * 64;
    const float* Vg = g_qkv + (size_t)b * S_ * QKVW + 2560 + kh * 64;

#pragma unroll
    for (int i = 0; i < 8; i++) {
        int idx = tid + i * 256;
        int r = idx >> 4, c4 = (idx & 15) * 4;
        cp_async16(Qs + r * FA_PAD + c4, Qg + (size_t)(qBase + r) * QKVW + c4);
    }
    CP_COMMIT();

    float o[8][4];
#pragma unroll
    for (int df = 0; df < 8; df++)
#pragma unroll
        for (int i = 0; i < 4; i++) o[df][i] = 0.f;
    float m_run[2] = {-INFINITY, -INFINITY};
    float l_run[2] = {0.f, 0.f};

    const int nTiles = 2 * qt + 2;
    const int rowMaxW = qBase + w * 16 + 15;

    for (int jt = 0; jt < nTiles; jt++) {
        __syncthreads();

#pragma unroll
        for (int i = 0; i < 4; i++) {
            int idx = tid + i * 256;
            int r = idx >> 4, c4 = (idx & 15) * 4;
            cp_async16(Ks + r * FA_PAD + c4, Kg + (size_t)(jt * 64 + r) * QKVW + c4);
        }
        CP_COMMIT();
        // V tile transposed + tf32-rounded: Vts[d][key]
#pragma unroll
        for (int i = 0; i < 4; i++) {
            int idx = tid + i * 256;
            int r = idx >> 4, d4 = (idx & 15) * 4;
            float4 v = *(const float4*)(Vg + (size_t)(jt * 64 + r) * QKVW + d4);
            Vts[(d4 + 0) * FA_PAD + r] = roundtf(v.x);
            Vts[(d4 + 1) * FA_PAD + r] = roundtf(v.y);
            Vts[(d4 + 2) * FA_PAD + r] = roundtf(v.z);
            Vts[(d4 + 3) * FA_PAD + r] = roundtf(v.w);
        }
        CP_WAIT(0);
        __syncthreads();

        if (jt * 64 <= rowMaxW) {
            // ---- S = Q @ K^T (raw-bit tf32 fragments) ----
            float s[8][4];
#pragma unroll
            for (int nf = 0; nf < 8; nf++)
#pragma unroll
                for (int i = 0; i < 4; i++) s[nf][i] = 0.f;

            const uint32_t* Qu = (const uint32_t*)Qs;
            const uint32_t* Ku = (const uint32_t*)Ks;
#pragma unroll
            for (int ks = 0; ks < 8; ks++) {
                const uint32_t* ap = Qu + (w * 16 + gid) * FA_PAD + ks * 8 + tig;
                uint32_t af[4];
                af[0] = ap[0];
                af[1] = ap[8 * FA_PAD];
                af[2] = ap[4];
                af[3] = ap[8 * FA_PAD + 4];
#pragma unroll
                for (int nf = 0; nf < 8; nf++) {
                    const uint32_t* bp = Ku + (nf * 8 + gid) * FA_PAD + ks * 8 + tig;
                    mma_tf32(s[nf], af, bp[0], bp[4]);
                }
            }

            const int r0 = qBase + w * 16 + gid;
            const int r1 = r0 + 8;
            const int cb = jt * 64;
#pragma unroll
            for (int nf = 0; nf < 8; nf++) {
                int c0 = cb + nf * 8 + 2 * tig;
                s[nf][0] = (c0     > r0) ? -1e30f : s[nf][0] * 0.125f;
                s[nf][1] = (c0 + 1 > r0) ? -1e30f : s[nf][1] * 0.125f;
                s[nf][2] = (c0     > r1) ? -1e30f : s[nf][2] * 0.125f;
                s[nf][3] = (c0 + 1 > r1) ? -1e30f : s[nf][3] * 0.125f;
            }

            float mx0 = -INFINITY, mx1 = -INFINITY;
#pragma unroll
            for (int nf = 0; nf < 8; nf++) {
                mx0 = fmaxf(mx0, fmaxf(s[nf][0], s[nf][1]));
                mx1 = fmaxf(mx1, fmaxf(s[nf][2], s[nf][3]));
            }
#pragma unroll
            for (int off = 1; off < 4; off <<= 1) {
                mx0 = fmaxf(mx0, __shfl_xor_sync(0xffffffffu, mx0, off));
                mx1 = fmaxf(mx1, __shfl_xor_sync(0xffffffffu, mx1, off));
            }
            const float mn0 = fmaxf(m_run[0], mx0);
            const float mn1 = fmaxf(m_run[1], mx1);
            const float al0 = expf(m_run[0] - mn0);
            const float al1 = expf(m_run[1] - mn1);
            m_run[0] = mn0; m_run[1] = mn1;

            float rs0 = 0.f, rs1 = 0.f;
#pragma unroll
            for (int nf = 0; nf < 8; nf++) {
                float p0 = expf(s[nf][0] - mn0);
                float p1 = expf(s[nf][1] - mn0);
                float p2 = expf(s[nf][2] - mn1);
                float p3 = expf(s[nf][3] - mn1);
                s[nf][0] = p0; s[nf][1] = p1; s[nf][2] = p2; s[nf][3] = p3;
                rs0 += p0 + p1;
                rs1 += p2 + p3;
            }
#pragma unroll
            for (int off = 1; off < 4; off <<= 1) {
                rs0 += __shfl_xor_sync(0xffffffffu, rs0, off);
                rs1 += __shfl_xor_sync(0xffffffffu, rs1, off);
            }
            l_run[0] = l_run[0] * al0 + rs0;
            l_run[1] = l_run[1] * al1 + rs1;
#pragma unroll
            for (int df = 0; df < 8; df++) {
                o[df][0] *= al0; o[df][1] *= al0;
                o[df][2] *= al1; o[df][3] *= al1;
            }

            // ---- write P (tf32-rounded; this warp's rows only) ----
            float* pp0 = Ps + (w * 16 + gid) * FA_PAD;
            float* pp1 = pp0 + 8 * FA_PAD;
#pragma unroll
            for (int nf = 0; nf < 8; nf++) {
                *(float2*)(pp0 + nf * 8 + 2 * tig) =
                    make_float2(roundtf(s[nf][0]), roundtf(s[nf][1]));
                *(float2*)(pp1 + nf * 8 + 2 * tig) =
                    make_float2(roundtf(s[nf][2]), roundtf(s[nf][3]));
            }
            __syncwarp();

            // ---- O += P @ V (raw-bit fragments) ----
            const uint32_t* Pu = (const uint32_t*)Ps;
            const uint32_t* Vu = (const uint32_t*)Vts;
#pragma unroll
            for (int ks = 0; ks < 8; ks++) {
                const uint32_t* ap = Pu + (w * 16 + gid) * FA_PAD + ks * 8 + tig;
                uint32_t af[4];
                af[0] = ap[0];
                af[1] = ap[8 * FA_PAD];
                af[2] = ap[4];
                af[3] = ap[8 * FA_PAD + 4];
#pragma unroll
                for (int df = 0; df < 8; df++) {
                    const uint32_t* bp = Vu + (df * 8 + gid) * FA_PAD + ks * 8 + tig;
                    mma_tf32(o[df], af, bp[0], bp[4]);
                }
            }
        }
    }

    // Epilogue: normalize, round to tf32 (feeds the Wo GEMM), store.
    const float il0 = 1.0f / l_run[0];
    const float il1 = 1.0f / l_run[1];
    const int r0 = qBase + w * 16 + gid;
    float* Og0 = g_attn + ((size_t)b * S_ + r0) * (NH_ * DH_) + h * 64;
    float* Og1 = Og0 + (size_t)8 * (NH_ * DH_);
#pragma unroll
    for (int df = 0; df < 8; df++) {
        *(float2*)(Og0 + df * 8 + 2 * tig) =
            make_float2(roundtf(o[df][0] * il0), roundtf(o[df][1] * il0));
        *(float2*)(Og1 + df * 8 + 2 * tig) =
            make_float2(roundtf(o[df][2] * il1), roundtf(o[df][3] * il1));
    }
}

// ---------------------------------------------------------------------------
// Launch
// ---------------------------------------------------------------------------
extern "C" void kernel_launch(void* const* d_in, const int* in_sizes, int n_in,
                              void* d_out, int out_size)
{
    const float* X   = (const float*)d_in[0];
    const int*   pos = (const int*)d_in[1];
    const float* Wq  = (const float*)d_in[2];
    const float* Wk  = (const float*)d_in[3];
    const float* Wv  = (const float*)d_in[4];
    const float* Wo  = (const float*)d_in[5];
    float* out = (float*)d_out;

    float *qkv_p, *attn_p, *xr_p, *w_p;
    cudaGetSymbolAddress((void**)&qkv_p, g_qkv);
    cudaGetSymbolAddress((void**)&attn_p, g_attn);
    cudaGetSymbolAddress((void**)&xr_p, g_xr);
    cudaGetSymbolAddress((void**)&w_p, g_w);

    cudaFuncSetAttribute(gemm_tf32, cudaFuncAttributeMaxDynamicSharedMemorySize, GEMM_SMEM);
    cudaFuncSetAttribute(flash_attn_tc, cudaFuncAttributeMaxDynamicSharedMemorySize, FA_SMEM);

    // Pre-round inputs once (no cvt in mma inner loops)
    round_x<<<(B_ * S_ * H_ / 4) / 256, 256>>>((const float4*)X, (float4*)xr_p);
    pack_qkv_w<<<2048, 256>>>((const float4*)Wq, (const float4*)Wk,
                              (const float4*)Wv, (float4*)w_p);
    round_x<<<(H_ * H_ / 4) / 256, 256>>>((const float4*)Wo,
                                          (float4*)(w_p + (size_t)2048 * QKVW));

    // Fused QKV projection: qkv[4096,3072] = Xr @ [Wq|Wk|Wv]
    gemm_tf32<<<dim3(24, 32), 128, GEMM_SMEM>>>(xr_p, w_p, qkv_p, 2048, QKVW, QKVW);

    // RoPE on Q and K in place (tf32-rounded outputs)
    rope_kernel<<<B_ * S_, 256>>>(pos);

    // Tensor-core flash attention
    flash_attn_tc<<<dim3(S_ / 128, NH_, B_), 256, FA_SMEM>>>();

    // Output projection: out = attn @ Wo
    gemm_tf32<<<dim3(16, 32), 128, GEMM_SMEM>>>(attn_p, w_p + (size_t)2048 * QKVW,
                                                out, 2048, 2048, 2048);
}

// round 12
// speedup vs baseline: 3.3395x; 1.0181x over previous
#include <cuda_runtime.h>
#include <math.h>
#include <stdint.h>

// Problem constants
#define B_ 2
#define S_ 2048
#define H_ 2048
#define NH_ 32
#define NKV_ 8
#define DH_ 64
#define NREP_ 4
#define QKVW 3072   // NH*DH + 2*NKV*DH

// Scratch (device globals: no allocation allowed)
__device__ float g_qkv[(size_t)B_ * S_ * QKVW];          // Q | K | V per token (tf32-rounded after RoPE)
__device__ float g_attn[(size_t)B_ * S_ * NH_ * DH_];    // attention output (tf32-rounded)
__device__ float g_xr[(size_t)B_ * S_ * H_];             // X rounded to tf32
__device__ float g_w[(size_t)(QKVW + H_) * H_];          // [Wq|Wk|Wv] packed [2048][3072], then Wo [2048][2048]

// ---------------------------------------------------------------------------
// Helpers
// ---------------------------------------------------------------------------
__device__ __forceinline__ void cp_async16(void* smem, const float* gmem) {
    uint32_t s = (uint32_t)__cvta_generic_to_shared(smem);
    asm volatile("cp.async.cg.shared.global [%0], [%1], 16;\n" :: "r"(s), "l"(gmem));
}
#define CP_COMMIT() asm volatile("cp.async.commit_group;\n" ::: "memory")
#define CP_WAIT(n)  asm volatile("cp.async.wait_group %0;\n" :: "n"(n) : "memory")

__device__ __forceinline__ uint32_t f2tf32(float x) {
    uint32_t r;
    asm("cvt.rna.tf32.f32 %0, %1;" : "=r"(r) : "f"(x));
    return r;
}
__device__ __forceinline__ float roundtf(float x) { return __uint_as_float(f2tf32(x)); }

__device__ __forceinline__ void mma_tf32(float* c, const uint32_t* a, uint32_t b0, uint32_t b1) {
    asm volatile(
        "mma.sync.aligned.m16n8k8.row.col.f32.tf32.tf32.f32 "
        "{%0,%1,%2,%3}, {%4,%5,%6,%7}, {%8,%9}, {%0,%1,%2,%3};"
        : "+f"(c[0]), "+f"(c[1]), "+f"(c[2]), "+f"(c[3])
        : "r"(a[0]), "r"(a[1]), "r"(a[2]), "r"(a[3]), "r"(b0), "r"(b1));
}

// ---------------------------------------------------------------------------
// Prep kernels: all tf32 rounding happens HERE, never in mma inner loops.
// ---------------------------------------------------------------------------
__global__ void round_x(const float4* __restrict__ in, float4* __restrict__ out)
{
    int i = blockIdx.x * blockDim.x + threadIdx.x;
    float4 v = in[i];
    v.x = roundtf(v.x); v.y = roundtf(v.y); v.z = roundtf(v.z); v.w = roundtf(v.w);
    out[i] = v;
}

// Pack + round [Wq|Wk|Wv] row-wise into g_w[0 .. 2048*3072). grid.x = 2048 rows.
__global__ void pack_qkv_w(const float4* __restrict__ Wq, const float4* __restrict__ Wk,
                           const float4* __restrict__ Wv, float4* __restrict__ out)
{
    const int k = blockIdx.x;                      // row 0..2047
    float4* orow = out + (size_t)k * (QKVW / 4);   // 768 float4s
    for (int c = threadIdx.x; c < QKVW / 4; c += blockDim.x) {
        float4 v;
        if (c < 512)       v = Wq[(size_t)k * 512 + c];
        else if (c < 640)  v = Wk[(size_t)k * 128 + (c - 512)];
        else               v = Wv[(size_t)k * 128 + (c - 640)];
        v.x = roundtf(v.x); v.y = roundtf(v.y); v.z = roundtf(v.z); v.w = roundtf(v.w);
        orow[c] = v;
    }
}

// ---------------------------------------------------------------------------
// tf32 tensor-core GEMM: C[M,N] = A[M,K] @ W[K,N]. Inputs PRE-ROUNDED to tf32.
// BM=BN=128, BK=32, 128 threads = 4 warps (64x64 warp tiles, 1.0 LDS/mma),
// THREE-stage cp.async pipeline: CP_WAIT finds its chunk already resident.
// A stride 36, B stride 136 -> all fragment LDS conflict-free.
// ---------------------------------------------------------------------------
#define ASZ (128 * 36)
#define BSTR 136
#define BSZ (32 * BSTR)
#define STGF (ASZ + BSZ)               // floats per stage
#define GEMM_SMEM (3 * STGF * 4)       // 107,520 B -> 2 CTAs/SM

__device__ __forceinline__ void gemm_load_tiles(
    const float* __restrict__ A, const float* __restrict__ W,
    float* stage, int K, int N, int mBase, int nBase, int k0, int tid)
{
    float* as = stage;
    float* bs = stage + ASZ;
#pragma unroll
    for (int i = 0; i < 8; i++) {                    // A tile: 128 x 32
        int idx = tid + i * 128;
        int r = idx >> 3, c4 = (idx & 7) * 4;
        cp_async16(as + r * 36 + c4, A + (size_t)(mBase + r) * K + k0 + c4);
    }
#pragma unroll
    for (int i = 0; i < 8; i++) {                    // B tile: 32 x 128
        int idx = tid + i * 128;
        int r = idx >> 5, n4 = (idx & 31) * 4;
        cp_async16(bs + r * BSTR + n4, W + (size_t)(k0 + r) * N + nBase + n4);
    }
}

__global__ __launch_bounds__(128, 2) void gemm_tf32(
    const float* __restrict__ A, const float* __restrict__ W,
    float* __restrict__ C, int K, int N, int ldc)
{
    extern __shared__ float sm[];

    const int tid = threadIdx.x;
    const int lane = tid & 31;
    const int wid = tid >> 5;
    const int wm = wid & 1;          // 2 warps on M: 64 rows each
    const int wn = wid >> 1;         // 2 warps on N: 64 cols each
    const int gid = lane >> 2;       // 0..7
    const int tig = lane & 3;        // 0..3
    const int mBase = blockIdx.y * 128;
    const int nBase = blockIdx.x * 128;

    float acc[4][8][4];
#pragma unroll
    for (int mt = 0; mt < 4; mt++)
#pragma unroll
        for (int nt = 0; nt < 8; nt++)
#pragma unroll
            for (int i = 0; i < 4; i++) acc[mt][nt][i] = 0.f;

    const int T = K >> 5;

    gemm_load_tiles(A, W, sm,            K, N, mBase, nBase, 0,  tid);
    CP_COMMIT();
    gemm_load_tiles(A, W, sm + STGF,     K, N, mBase, nBase, 32, tid);
    CP_COMMIT();

    int stage = 0;
    for (int t = 0; t < T; t++) {
        CP_WAIT(1);                 // chunk t resident (loaded 2 iters ago)
        __syncthreads();

        if (t + 2 < T) {            // prefetch chunk t+2 into the stage freed by chunk t-1
            int ps = stage + 2; if (ps >= 3) ps -= 3;
            gemm_load_tiles(A, W, sm + ps * STGF, K, N, mBase, nBase, (t + 2) * 32, tid);
            CP_COMMIT();
        }

        const uint32_t* as = (const uint32_t*)(sm + stage * STGF);
        const uint32_t* bs = as + ASZ;

#pragma unroll
        for (int ks = 0; ks < 4; ks++) {
            const int kk = ks * 8;
            uint32_t af[4][4];
#pragma unroll
            for (int mt = 0; mt < 4; mt++) {
                const uint32_t* ap = as + (wm * 64 + mt * 16 + gid) * 36 + kk + tig;
                af[mt][0] = ap[0];
                af[mt][1] = ap[8 * 36];
                af[mt][2] = ap[4];
                af[mt][3] = ap[8 * 36 + 4];
            }
#pragma unroll
            for (int nt = 0; nt < 8; nt++) {
                const uint32_t* bp = bs + (kk + tig) * BSTR + wn * 64 + nt * 8 + gid;
                uint32_t b0 = bp[0];
                uint32_t b1 = bp[4 * BSTR];
#pragma unroll
                for (int mt = 0; mt < 4; mt++)
                    mma_tf32(acc[mt][nt], af[mt], b0, b1);
            }
        }
        if (++stage == 3) stage = 0;
    }

#pragma unroll
    for (int mt = 0; mt < 4; mt++) {
#pragma unroll
        for (int nt = 0; nt < 8; nt++) {
            const int r = mBase + wm * 64 + mt * 16 + gid;
            const int c = nBase + wn * 64 + nt * 8 + 2 * tig;
            float2 v0 = make_float2(acc[mt][nt][0], acc[mt][nt][1]);
            float2 v1 = make_float2(acc[mt][nt][2], acc[mt][nt][3]);
            *(float2*)(C + (size_t)r * ldc + c) = v0;
            *(float2*)(C + (size_t)(r + 8) * ldc + c) = v1;
        }
    }
}

// ---------------------------------------------------------------------------
// RoPE in place on Q (heads 0..31) and K (heads 32..39); outputs tf32-rounded.
// ---------------------------------------------------------------------------
__global__ void rope_kernel(const int* __restrict__ pos_ids)
{
    const int bs = blockIdx.x;
    const float p = (float)pos_ids[bs];
    float* base = g_qkv + (size_t)bs * QKVW;

    const float NEG_L2T_OVER_32 = -0.41524101186092029f;   // -log2(10000)/32

    for (int idx = threadIdx.x; idx < (NH_ + NKV_) * 32; idx += blockDim.x) {
        const int head = idx >> 5;
        const int i = idx & 31;
        const float inv = exp2f((float)i * NEG_L2T_OVER_32);
        const float ang = p * inv;
        float sv, cv;
        sincosf(ang, &sv, &cv);
        float* hp = base + head * DH_;
        const float x1 = hp[i];
        const float x2 = hp[i + 32];
        hp[i]      = roundtf(x1 * cv - x2 * sv);
        hp[i + 32] = roundtf(x2 * cv + x1 * sv);
    }
}

// ---------------------------------------------------------------------------
// Tensor-core flash attention (tf32 mma.sync): grid (S/128, NH, B), 128 thr.
// 4 warps, warp owns 32 query rows (2 m16 tiles) x 64 keys: per ks the warp
// does 24 LDS for 16 mmas (1.5 LDS/mma) and each B fragment feeds 2 mmas.
// All operands pre-rounded; inner loops pure LDS+MMA. Numerics identical.
// ---------------------------------------------------------------------------
#define FA_PAD 68
#define FQ (128 * FA_PAD)
#define FK (64 * FA_PAD)
#define FV (64 * FA_PAD)
#define FP (128 * FA_PAD)
#define FA_SMEM ((FQ + FK + FV + FP) * 4)

__global__ __launch_bounds__(128, 2) void flash_attn_tc()
{
    extern __shared__ float smf[];
    float* Qs  = smf;
    float* Ks  = smf + FQ;
    float* Vts = Ks + FK;
    float* Ps  = Vts + FV;

    const int qt = blockIdx.x, h = blockIdx.y, b = blockIdx.z;
    const int kh = h >> 2;
    const int tid  = threadIdx.x;
    const int lane = tid & 31;
    const int w    = tid >> 5;      // 0..3, warp owns rows w*32..w*32+31
    const int gid  = lane >> 2;
    const int tig  = lane & 3;
    const int qBase = qt * 128;

    const float* Qg = g_qkv + (size_t)b * S_ * QKVW + h * 64;
    const float* Kg = g_qkv + (size_t)b * S_ * QKVW + 2048 + kh * 64;
    const float* Vg = g_qkv + (size_t)b * S_ * QKVW + 2560 + kh * 64;

    // Q tile 128x64 -> 2048 float4s / 128 threads = 16 iters
#pragma unroll
    for (int i = 0; i < 16; i++) {
        int idx = tid + i * 128;
        int r = idx >> 4, c4 = (idx & 15) * 4;
        cp_async16(Qs + r * FA_PAD + c4, Qg + (size_t)(qBase + r) * QKVW + c4);
    }
    CP_COMMIT();

    float o[2][8][4];
#pragma unroll
    for (int mt = 0; mt < 2; mt++)
#pragma unroll
        for (int df = 0; df < 8; df++)
#pragma unroll
            for (int i = 0; i < 4; i++) o[mt][df][i] = 0.f;
    float m_run[2][2] = {{-INFINITY, -INFINITY}, {-INFINITY, -INFINITY}};
    float l_run[2][2] = {{0.f, 0.f}, {0.f, 0.f}};

    const int nTiles = 2 * qt + 2;
    const int rowMaxW = qBase + w * 32 + 31;

    for (int jt = 0; jt < nTiles; jt++) {
        __syncthreads();

        // K tile 64x64 -> 1024 float4s / 128 threads = 8 iters
#pragma unroll
        for (int i = 0; i < 8; i++) {
            int idx = tid + i * 128;
            int r = idx >> 4, c4 = (idx & 15) * 4;
            cp_async16(Ks + r * FA_PAD + c4, Kg + (size_t)(jt * 64 + r) * QKVW + c4);
        }
        CP_COMMIT();
        // V tile transposed + tf32-rounded: Vts[d][key]
#pragma unroll
        for (int i = 0; i < 8; i++) {
            int idx = tid + i * 128;
            int r = idx >> 4, d4 = (idx & 15) * 4;
            float4 v = *(const float4*)(Vg + (size_t)(jt * 64 + r) * QKVW + d4);
            Vts[(d4 + 0) * FA_PAD + r] = roundtf(v.x);
            Vts[(d4 + 1) * FA_PAD + r] = roundtf(v.y);
            Vts[(d4 + 2) * FA_PAD + r] = roundtf(v.z);
            Vts[(d4 + 3) * FA_PAD + r] = roundtf(v.w);
        }
        CP_WAIT(0);
        __syncthreads();

        if (jt * 64 <= rowMaxW) {
            // ---- S = Q @ K^T (2 m16 tiles x 64 keys) ----
            float s[2][8][4];
#pragma unroll
            for (int mt = 0; mt < 2; mt++)
#pragma unroll
                for (int nf = 0; nf < 8; nf++)
#pragma unroll
                    for (int i = 0; i < 4; i++) s[mt][nf][i] = 0.f;

            const uint32_t* Qu = (const uint32_t*)Qs;
            const uint32_t* Ku = (const uint32_t*)Ks;
#pragma unroll
            for (int ks = 0; ks < 8; ks++) {
                uint32_t af[2][4];
#pragma unroll
                for (int mt = 0; mt < 2; mt++) {
                    const uint32_t* ap = Qu + (w * 32 + mt * 16 + gid) * FA_PAD + ks * 8 + tig;
                    af[mt][0] = ap[0];
                    af[mt][1] = ap[8 * FA_PAD];
                    af[mt][2] = ap[4];
                    af[mt][3] = ap[8 * FA_PAD + 4];
                }
#pragma unroll
                for (int nf = 0; nf < 8; nf++) {
                    const uint32_t* bp = Ku + (nf * 8 + gid) * FA_PAD + ks * 8 + tig;
                    uint32_t b0 = bp[0];
                    uint32_t b1 = bp[4];
                    mma_tf32(s[0][nf], af[0], b0, b1);
                    mma_tf32(s[1][nf], af[1], b0, b1);
                }
            }

            const int cb = jt * 64;
#pragma unroll
            for (int mt = 0; mt < 2; mt++) {
                const int r0 = qBase + w * 32 + mt * 16 + gid;
                const int r1 = r0 + 8;
                // ---- scale + causal mask ----
#pragma unroll
                for (int nf = 0; nf < 8; nf++) {
                    int c0 = cb + nf * 8 + 2 * tig;
                    s[mt][nf][0] = (c0     > r0) ? -1e30f : s[mt][nf][0] * 0.125f;
                    s[mt][nf][1] = (c0 + 1 > r0) ? -1e30f : s[mt][nf][1] * 0.125f;
                    s[mt][nf][2] = (c0     > r1) ? -1e30f : s[mt][nf][2] * 0.125f;
                    s[mt][nf][3] = (c0 + 1 > r1) ? -1e30f : s[mt][nf][3] * 0.125f;
                }

                // ---- online softmax (quad reductions) ----
                float mx0 = -INFINITY, mx1 = -INFINITY;
#pragma unroll
                for (int nf = 0; nf < 8; nf++) {
                    mx0 = fmaxf(mx0, fmaxf(s[mt][nf][0], s[mt][nf][1]));
                    mx1 = fmaxf(mx1, fmaxf(s[mt][nf][2], s[mt][nf][3]));
                }
#pragma unroll
                for (int off = 1; off < 4; off <<= 1) {
                    mx0 = fmaxf(mx0, __shfl_xor_sync(0xffffffffu, mx0, off));
                    mx1 = fmaxf(mx1, __shfl_xor_sync(0xffffffffu, mx1, off));
                }
                const float mn0 = fmaxf(m_run[mt][0], mx0);
                const float mn1 = fmaxf(m_run[mt][1], mx1);
                const float al0 = expf(m_run[mt][0] - mn0);
                const float al1 = expf(m_run[mt][1] - mn1);
                m_run[mt][0] = mn0; m_run[mt][1] = mn1;

                float rs0 = 0.f, rs1 = 0.f;
#pragma unroll
                for (int nf = 0; nf < 8; nf++) {
                    float p0 = expf(s[mt][nf][0] - mn0);
                    float p1 = expf(s[mt][nf][1] - mn0);
                    float p2 = expf(s[mt][nf][2] - mn1);
                    float p3 = expf(s[mt][nf][3] - mn1);
                    s[mt][nf][0] = p0; s[mt][nf][1] = p1; s[mt][nf][2] = p2; s[mt][nf][3] = p3;
                    rs0 += p0 + p1;
                    rs1 += p2 + p3;
                }
#pragma unroll
                for (int off = 1; off < 4; off <<= 1) {
                    rs0 += __shfl_xor_sync(0xffffffffu, rs0, off);
                    rs1 += __shfl_xor_sync(0xffffffffu, rs1, off);
                }
                l_run[mt][0] = l_run[mt][0] * al0 + rs0;
                l_run[mt][1] = l_run[mt][1] * al1 + rs1;
#pragma unroll
                for (int df = 0; df < 8; df++) {
                    o[mt][df][0] *= al0; o[mt][df][1] *= al0;
                    o[mt][df][2] *= al1; o[mt][df][3] *= al1;
                }

                // ---- write P (tf32-rounded; this warp's rows only) ----
                float* pp0 = Ps + (w * 32 + mt * 16 + gid) * FA_PAD;
                float* pp1 = pp0 + 8 * FA_PAD;
#pragma unroll
                for (int nf = 0; nf < 8; nf++) {
                    *(float2*)(pp0 + nf * 8 + 2 * tig) =
                        make_float2(roundtf(s[mt][nf][0]), roundtf(s[mt][nf][1]));
                    *(float2*)(pp1 + nf * 8 + 2 * tig) =
                        make_float2(roundtf(s[mt][nf][2]), roundtf(s[mt][nf][3]));
                }
            }
            __syncwarp();

            // ---- O += P @ V (raw-bit fragments) ----
            const uint32_t* Pu = (const uint32_t*)Ps;
            const uint32_t* Vu = (const uint32_t*)Vts;
#pragma unroll
            for (int ks = 0; ks < 8; ks++) {
                uint32_t af[2][4];
#pragma unroll
                for (int mt = 0; mt < 2; mt++) {
                    const uint32_t* ap = Pu + (w * 32 + mt * 16 + gid) * FA_PAD + ks * 8 + tig;
                    af[mt][0] = ap[0];
                    af[mt][1] = ap[8 * FA_PAD];
                    af[mt][2] = ap[4];
                    af[mt][3] = ap[8 * FA_PAD + 4];
                }
#pragma unroll
                for (int df = 0; df < 8; df++) {
                    const uint32_t* bp = Vu + (df * 8 + gid) * FA_PAD + ks * 8 + tig;
                    uint32_t b0 = bp[0];
                    uint32_t b1 = bp[4];
                    mma_tf32(o[0][df], af[0], b0, b1);
                    mma_tf32(o[1][df], af[1], b0, b1);
                }
            }
        }
    }

    // Epilogue: normalize, round to tf32 (feeds the Wo GEMM), store.
#pragma unroll
    for (int mt = 0; mt < 2; mt++) {
        const float il0 = 1.0f / l_run[mt][0];
        const float il1 = 1.0f / l_run[mt][1];
        const int r0 = qBase + w * 32 + mt * 16 + gid;
        float* Og0 = g_attn + ((size_t)b * S_ + r0) * (NH_ * DH_) + h * 64;
        float* Og1 = Og0 + (size_t)8 * (NH_ * DH_);
#pragma unroll
        for (int df = 0; df < 8; df++) {
            *(float2*)(Og0 + df * 8 + 2 * tig) =
                make_float2(roundtf(o[mt][df][0] * il0), roundtf(o[mt][df][1] * il0));
            *(float2*)(Og1 + df * 8 + 2 * tig) =
                make_float2(roundtf(o[mt][df][2] * il1), roundtf(o[mt][df][3] * il1));
        }
    }
}

// ---------------------------------------------------------------------------
// Launch
// ---------------------------------------------------------------------------
extern "C" void kernel_launch(void* const* d_in, const int* in_sizes, int n_in,
                              void* d_out, int out_size)
{
    const float* X   = (const float*)d_in[0];
    const int*   pos = (const int*)d_in[1];
    const float* Wq  = (const float*)d_in[2];
    const float* Wk  = (const float*)d_in[3];
    const float* Wv  = (const float*)d_in[4];
    const float* Wo  = (const float*)d_in[5];
    float* out = (float*)d_out;

    float *qkv_p, *attn_p, *xr_p, *w_p;
    cudaGetSymbolAddress((void**)&qkv_p, g_qkv);
    cudaGetSymbolAddress((void**)&attn_p, g_attn);
    cudaGetSymbolAddress((void**)&xr_p, g_xr);
    cudaGetSymbolAddress((void**)&w_p, g_w);

    cudaFuncSetAttribute(gemm_tf32, cudaFuncAttributeMaxDynamicSharedMemorySize, GEMM_SMEM);
    cudaFuncSetAttribute(flash_attn_tc, cudaFuncAttributeMaxDynamicSharedMemorySize, FA_SMEM);

    // Pre-round inputs once (no cvt in mma inner loops)
    round_x<<<(B_ * S_ * H_ / 4) / 256, 256>>>((const float4*)X, (float4*)xr_p);
    pack_qkv_w<<<2048, 256>>>((const float4*)Wq, (const float4*)Wk,
                              (const float4*)Wv, (float4*)w_p);
    round_x<<<(H_ * H_ / 4) / 256, 256>>>((const float4*)Wo,
                                          (float4*)(w_p + (size_t)2048 * QKVW));

    // Fused QKV projection: qkv[4096,3072] = Xr @ [Wq|Wk|Wv]
    gemm_tf32<<<dim3(24, 32), 128, GEMM_SMEM>>>(xr_p, w_p, qkv_p, 2048, QKVW, QKVW);

    // RoPE on Q and K in place (tf32-rounded outputs)
    rope_kernel<<<B_ * S_, 256>>>(pos);

    // Tensor-core flash attention (4 warps, 32-row warp tiles)
    flash_attn_tc<<<dim3(S_ / 128, NH_, B_), 128, FA_SMEM>>>();

    // Output projection: out = attn @ Wo
    gemm_tf32<<<dim3(16, 32), 128, GEMM_SMEM>>>(attn_p, w_p + (size_t)2048 * QKVW,
                                                out, 2048, 2048, 2048);
}